// round 4
// baseline (speedup 1.0000x reference)
#include <cuda_runtime.h>
#include <cuda_bf16.h>
#include <cstdint>

#define N_NODES  100000
#define N_EDGES  1600000
#define N_GRAPHS 1000
#define D        128
#define NOUT     6

// ---------------- scratch (static device globals; no allocs allowed) ----------
__device__ __align__(16) unsigned g_bufA[N_NODES * D];   // packed (hi,lo) bf16 or f32
__device__ __align__(16) unsigned g_bufB[N_NODES * D];
__device__ int   g_rowptr[N_NODES + 1];
__device__ int   g_pos[N_NODES];          // histogram counts, then fill cursors
__device__ int   g_col[N_EDGES];
__device__ __align__(16) float g_pooled[N_GRAPHS * D];
__device__ int   g_cnt[N_GRAPHS];
__device__ int   g_flag;                   // 1 = indices are int64, 0 = int32
__device__ __align__(16) __nv_bfloat16 g_Whi[4 * D * D];
__device__ __align__(16) __nv_bfloat16 g_Wlo[4 * D * D];

// ---------------- helpers -----------------------------------------------------
__device__ __forceinline__ long long ld_idx(const void* p, long long i, int wide) {
    return wide ? ((const long long*)p)[i] : (long long)((const int*)p)[i];
}
// pack float -> (hi bf16 in low 16, lo bf16 in high 16)
__device__ __forceinline__ unsigned packf(float x) {
    __nv_bfloat16 h = __float2bfloat16(x);
    float hf = __bfloat162float(h);
    __nv_bfloat16 l = __float2bfloat16(x - hf);
    return (unsigned)__bfloat16_as_ushort(h) | ((unsigned)__bfloat16_as_ushort(l) << 16);
}
// reconstruct f32 ~ hi + lo from packed word (bf16 = top 16 bits of f32)
__device__ __forceinline__ float unpackf(unsigned p) {
    return __uint_as_float(p << 16) + __uint_as_float(p & 0xFFFF0000u);
}

// zero scratch + dtype detect (thread 0 of block 0)
__global__ void k_zero_detect(const void* ei) {
    int i = blockIdx.x * blockDim.x + threadIdx.x;
    if (blockIdx.x == 0 && threadIdx.x == 0) {
        const int* p = (const int*)ei;
        int wide = 1;
        for (int k = 0; k < 64; k++)
            if (p[2 * k + 1] != 0) { wide = 0; break; }
        g_flag = wide;
    }
    int total = N_NODES + N_GRAPHS * D + N_GRAPHS;
    for (; i < total; i += gridDim.x * blockDim.x) {
        if (i < N_NODES) g_pos[i] = 0;
        else if (i < N_NODES + N_GRAPHS * D) g_pooled[i - N_NODES] = 0.0f;
        else g_cnt[i - N_NODES - N_GRAPHS * D] = 0;
    }
}

// histogram of dst
__global__ void k_hist(const void* ei) {
    int wide = g_flag;
    int e = blockIdx.x * blockDim.x + threadIdx.x;
    for (; e < N_EDGES; e += gridDim.x * blockDim.x) {
        int dst = (int)ld_idx(ei, (long long)N_EDGES + e, wide);
        atomicAdd(&g_pos[dst], 1);
    }
}

// single-block full scan: g_rowptr = exclusive prefix, g_pos = start cursors
#define CHUNK 98
__global__ void k_scanall() {
    __shared__ int s[1024];
    int t = threadIdx.x;
    int beg = t * CHUNK;
    int end = beg + CHUNK; if (end > N_NODES) end = N_NODES;
    int sum = 0;
    for (int i = beg; i < end; i++) sum += g_pos[i];
    s[t] = sum;
    __syncthreads();
    for (int off = 1; off < 1024; off <<= 1) {
        int v = (t >= off) ? s[t - off] : 0;
        __syncthreads();
        s[t] += v;
        __syncthreads();
    }
    int run = s[t] - sum;   // exclusive base for this chunk
    if (t == 0) g_rowptr[0] = 0;
    for (int i = beg; i < end; i++) {
        int c = g_pos[i];
        g_pos[i] = run;      // fill cursor = rowptr[i]
        run += c;
        g_rowptr[i + 1] = run;
    }
}

__global__ void k_fill(const void* ei) {
    int wide = g_flag;
    int e = blockIdx.x * blockDim.x + threadIdx.x;
    for (; e < N_EDGES; e += gridDim.x * blockDim.x) {
        int src = (int)ld_idx(ei, e, wide);
        int dst = (int)ld_idx(ei, (long long)N_EDGES + e, wide);
        int p = atomicAdd(&g_pos[dst], 1);
        g_col[p] = src;
    }
}

// split 4 weight matrices into bf16 hi/lo planes
__global__ void k_wprep(const float* __restrict__ Wa, const float* __restrict__ Wb,
                        const float* __restrict__ Wc, const float* __restrict__ Wd) {
    int idx = blockIdx.x * blockDim.x + threadIdx.x;
    if (idx >= 4 * D * D) return;
    int m = idx >> 14, j = idx & 16383;
    const float* W = (m == 0) ? Wa : (m == 1) ? Wb : (m == 2) ? Wc : Wd;
    float v = W[j];
    __nv_bfloat16 h = __float2bfloat16(v);
    g_Whi[idx] = h;
    g_Wlo[idx] = __float2bfloat16(v - __bfloat162float(h));
}

// agg1: f32 input -> packed output. warp per node, lane = 4 features.
__global__ void k_agg1(const float* __restrict__ in, unsigned* __restrict__ out) {
    int node = (blockIdx.x * blockDim.x + threadIdx.x) >> 5;
    int lane = threadIdx.x & 31;
    if (node >= N_NODES) return;
    const float4* in4 = (const float4*)in;
    float4 acc = in4[(long long)node * 32 + lane];
    int j = g_rowptr[node], end = g_rowptr[node + 1];
    for (; j + 2 <= end; j += 2) {
        int s0 = g_col[j], s1 = g_col[j + 1];
        float4 v0 = in4[(long long)s0 * 32 + lane];
        float4 v1 = in4[(long long)s1 * 32 + lane];
        acc.x += v0.x + v1.x; acc.y += v0.y + v1.y;
        acc.z += v0.z + v1.z; acc.w += v0.w + v1.w;
    }
    if (j < end) {
        float4 v = in4[(long long)g_col[j] * 32 + lane];
        acc.x += v.x; acc.y += v.y; acc.z += v.z; acc.w += v.w;
    }
    uint4 o = make_uint4(packf(acc.x), packf(acc.y), packf(acc.z), packf(acc.w));
    ((uint4*)out)[(long long)node * 32 + lane] = o;
}

// agg2: packed input -> packed output
__global__ void k_agg2(const unsigned* __restrict__ in, unsigned* __restrict__ out) {
    int node = (blockIdx.x * blockDim.x + threadIdx.x) >> 5;
    int lane = threadIdx.x & 31;
    if (node >= N_NODES) return;
    const uint4* in4 = (const uint4*)in;
    uint4 ps = in4[(long long)node * 32 + lane];
    float ax = unpackf(ps.x), ay = unpackf(ps.y), az = unpackf(ps.z), aw = unpackf(ps.w);
    int j = g_rowptr[node], end = g_rowptr[node + 1];
    for (; j + 2 <= end; j += 2) {
        int s0 = g_col[j], s1 = g_col[j + 1];
        uint4 p0 = in4[(long long)s0 * 32 + lane];
        uint4 p1 = in4[(long long)s1 * 32 + lane];
        ax += unpackf(p0.x) + unpackf(p1.x);
        ay += unpackf(p0.y) + unpackf(p1.y);
        az += unpackf(p0.z) + unpackf(p1.z);
        aw += unpackf(p0.w) + unpackf(p1.w);
    }
    if (j < end) {
        uint4 p = in4[(long long)g_col[j] * 32 + lane];
        ax += unpackf(p.x); ay += unpackf(p.y); az += unpackf(p.z); aw += unpackf(p.w);
    }
    uint4 o = make_uint4(packf(ax), packf(ay), packf(az), packf(aw));
    ((uint4*)out)[(long long)node * 32 + lane] = o;
}

// ---------------- tensor-core GEMM (bf16 3-term split, 64-row tiles) ----------
#define LDB 136
#define A_ELEMS (64 * LDB)      // 8704 per plane
#define W_ELEMS (128 * LDB)     // 17408 per plane
#define SMEM_GEMM ((2 * A_ELEMS + 2 * W_ELEMS) * 2)   // 104448 bytes

__device__ __forceinline__ void ldsm4(uint32_t& r0, uint32_t& r1, uint32_t& r2, uint32_t& r3, uint32_t addr) {
    asm volatile("ldmatrix.sync.aligned.m8n8.x4.shared.b16 {%0,%1,%2,%3}, [%4];"
                 : "=r"(r0), "=r"(r1), "=r"(r2), "=r"(r3) : "r"(addr));
}
__device__ __forceinline__ void ldsm4t(uint32_t& r0, uint32_t& r1, uint32_t& r2, uint32_t& r3, uint32_t addr) {
    asm volatile("ldmatrix.sync.aligned.m8n8.x4.trans.shared.b16 {%0,%1,%2,%3}, [%4];"
                 : "=r"(r0), "=r"(r1), "=r"(r2), "=r"(r3) : "r"(addr));
}
__device__ __forceinline__ void mma_bf16(float* c, uint32_t a0, uint32_t a1, uint32_t a2, uint32_t a3,
                                         uint32_t b0, uint32_t b1) {
    asm volatile("mma.sync.aligned.m16n8k16.row.col.f32.bf16.bf16.f32 "
                 "{%0,%1,%2,%3}, {%4,%5,%6,%7}, {%8,%9}, {%0,%1,%2,%3};"
                 : "+f"(c[0]), "+f"(c[1]), "+f"(c[2]), "+f"(c[3])
                 : "r"(a0), "r"(a1), "r"(a2), "r"(a3), "r"(b0), "r"(b1));
}

__global__ __launch_bounds__(256, 2)
void k_gemm2(const unsigned* __restrict__ Ain, const __nv_bfloat16* __restrict__ Whi,
             const __nv_bfloat16* __restrict__ Wlo, const float* __restrict__ bias,
             unsigned* __restrict__ Cout, int doRelu, int packOut) {
    extern __shared__ __nv_bfloat16 sm[];
    // layout (elems): [0, A_ELEMS) Ahi | [A_ELEMS, 2A) Alo | [2A, 2A+W) Whi | [.., +W) Wlo
    const int t = threadIdx.x;
    const int blockRow = blockIdx.x * 64;

    // stage A (packed -> separated hi/lo planes)
#pragma unroll
    for (int i = 0; i < 8; i++) {
        int lin = t + i * 256;          // 0..2047, 32 uint4 per row
        int row = lin >> 5;
        int q   = lin & 31;
        uint4 p = make_uint4(0u, 0u, 0u, 0u);
        long long gr = blockRow + row;
        if (gr < N_NODES) p = ((const uint4*)Ain)[gr * 32 + q];
        unsigned hi01 = __byte_perm(p.x, p.y, 0x5410);
        unsigned hi23 = __byte_perm(p.z, p.w, 0x5410);
        unsigned lo01 = __byte_perm(p.x, p.y, 0x7632);
        unsigned lo23 = __byte_perm(p.z, p.w, 0x7632);
        int o = row * LDB + q * 4;
        *(uint2*)&sm[o]           = make_uint2(hi01, hi23);
        *(uint2*)&sm[A_ELEMS + o] = make_uint2(lo01, lo23);
    }
    // stage W hi/lo planes (straight copy into padded layout)
#pragma unroll
    for (int i = 0; i < 8; i++) {
        int lin = t + i * 256;          // 0..2047 uint4 (8 bf16) per plane
        int row = lin >> 4;
        int c8  = (lin & 15) * 8;
        int o = row * LDB + c8;
        *(uint4*)&sm[2 * A_ELEMS + o]           = ((const uint4*)Whi)[lin];
        *(uint4*)&sm[2 * A_ELEMS + W_ELEMS + o] = ((const uint4*)Wlo)[lin];
    }
    __syncthreads();

    const int w = t >> 5, lane = t & 31;
    const int mbase = (w >> 1) * 16;
    const int nbase = (w & 1) * 64;
    const int lrow = lane & 15;
    const int lcol = (lane >> 4) * 8;

    float acc[8][4];
#pragma unroll
    for (int nf = 0; nf < 8; nf++)
#pragma unroll
        for (int r = 0; r < 4; r++) acc[nf][r] = 0.f;

    uint32_t sBase = (uint32_t)__cvta_generic_to_shared(sm);
    const int aOffs[3] = {0, 0, A_ELEMS};
    const int wOffs[3] = {2 * A_ELEMS, 2 * A_ELEMS + W_ELEMS, 2 * A_ELEMS};

#pragma unroll
    for (int pass = 0; pass < 3; pass++) {
        const int aOff = aOffs[pass];
        const int wOff = wOffs[pass];
#pragma unroll
        for (int kk = 0; kk < 8; kk++) {
            const int k0 = kk * 16;
            uint32_t a0, a1, a2, a3;
            ldsm4(a0, a1, a2, a3, sBase + 2u * (aOff + (mbase + lrow) * LDB + k0 + lcol));
            uint32_t b[4][4];
#pragma unroll
            for (int ni = 0; ni < 4; ni++)
                ldsm4t(b[ni][0], b[ni][1], b[ni][2], b[ni][3],
                       sBase + 2u * (wOff + (k0 + lrow) * LDB + nbase + ni * 16 + lcol));
#pragma unroll
            for (int ni = 0; ni < 4; ni++) {
                mma_bf16(acc[2 * ni],     a0, a1, a2, a3, b[ni][0], b[ni][1]);
                mma_bf16(acc[2 * ni + 1], a0, a1, a2, a3, b[ni][2], b[ni][3]);
            }
        }
    }

    // epilogue
    const int colb = nbase + 2 * (lane & 3);
    const int r0 = blockRow + mbase + (lane >> 2);
#pragma unroll
    for (int nf = 0; nf < 8; nf++) {
        float2 bb = *(const float2*)&bias[colb + nf * 8];
#pragma unroll
        for (int half = 0; half < 2; half++) {
            long long rr = r0 + half * 8;
            if (rr >= N_NODES) continue;
            float vx = acc[nf][half * 2 + 0] + bb.x;
            float vy = acc[nf][half * 2 + 1] + bb.y;
            if (doRelu) { vx = fmaxf(vx, 0.f); vy = fmaxf(vy, 0.f); }
            long long oidx = rr * 128 + colb + nf * 8;
            if (packOut) {
                *(uint2*)&Cout[oidx] = make_uint2(packf(vx), packf(vy));
            } else {
                *(float2*)&((float*)Cout)[oidx] = make_float2(vx, vy);
            }
        }
    }
}

// per-graph counts
__global__ void k_count(const void* batch) {
    int wide = g_flag;
    int n = blockIdx.x * blockDim.x + threadIdx.x;
    for (; n < N_NODES; n += gridDim.x * blockDim.x) {
        int g = (int)ld_idx(batch, n, wide);
        atomicAdd(&g_cnt[g], 1);
    }
}

#define NODES_PER_BLK 512
__global__ void k_pool(const float* __restrict__ h, const void* batch) {
    int wide = g_flag;
    int f = threadIdx.x;
    int base = blockIdx.x * NODES_PER_BLK;
    int end = base + NODES_PER_BLK;
    if (end > N_NODES) end = N_NODES;
    float run = 0.0f;
    int cur = -1;
    for (int n = base; n < end; n++) {
        int g = (int)ld_idx(batch, n, wide);
        if (g != cur) {
            if (cur >= 0) atomicAdd(&g_pooled[cur * D + f], run);
            cur = g;
            run = 0.0f;
        }
        run += h[(long long)n * D + f];
    }
    if (cur >= 0) atomicAdd(&g_pooled[cur * D + f], run);
}

__global__ void k_final(const float* __restrict__ Wlin, const float* __restrict__ blin,
                        float* __restrict__ out) {
    int g = blockIdx.x;
    int k = threadIdx.x; // 128
    float c = (float)g_cnt[g];
    if (c < 1.0f) c = 1.0f;
    float v = g_pooled[g * D + k] / c;
    __shared__ float red[128];
    for (int j = 0; j < NOUT; j++) {
        red[k] = v * Wlin[k * NOUT + j];
        __syncthreads();
        for (int s = 64; s > 0; s >>= 1) {
            if (k < s) red[k] += red[k + s];
            __syncthreads();
        }
        if (k == 0) out[g * NOUT + j] = red[0] + blin[j];
        __syncthreads();
    }
}

// ---------------- launch ------------------------------------------------------
extern "C" void kernel_launch(void* const* d_in, const int* in_sizes, int n_in,
                              void* d_out, int out_size) {
    const float* x    = (const float*)d_in[0];
    const void*  ei   = d_in[1];
    const void*  batch= d_in[2];
    const float* W1a  = (const float*)d_in[3];
    const float* b1a  = (const float*)d_in[4];
    const float* W1b  = (const float*)d_in[5];
    const float* b1b  = (const float*)d_in[6];
    const float* W2a  = (const float*)d_in[7];
    const float* b2a  = (const float*)d_in[8];
    const float* W2b  = (const float*)d_in[9];
    const float* b2b  = (const float*)d_in[10];
    const float* Wlin = (const float*)d_in[11];
    const float* blin = (const float*)d_in[12];
    float* out = (float*)d_out;

    unsigned* bufA; cudaGetSymbolAddress((void**)&bufA, g_bufA);
    unsigned* bufB; cudaGetSymbolAddress((void**)&bufB, g_bufB);
    __nv_bfloat16* whi; cudaGetSymbolAddress((void**)&whi, g_Whi);
    __nv_bfloat16* wlo; cudaGetSymbolAddress((void**)&wlo, g_Wlo);

    cudaFuncSetAttribute(k_gemm2, cudaFuncAttributeMaxDynamicSharedMemorySize, SMEM_GEMM);

    const int aggBlocks = (N_NODES * 32 + 255) / 256;
    const int gemmBlocks = (N_NODES + 63) / 64;   // 1563

    k_zero_detect<<<448, 512>>>(ei);
    k_hist<<<6250, 256>>>(ei);
    k_scanall<<<1, 1024>>>();
    k_fill<<<6250, 256>>>(ei);
    k_wprep<<<(4 * D * D + 255) / 256, 256>>>(W1a, W1b, W2a, W2b);

    // layer 1
    k_agg1<<<aggBlocks, 256>>>(x, bufA);
    k_gemm2<<<gemmBlocks, 256, SMEM_GEMM>>>(bufA, whi,             wlo,             b1a, bufB, 1, 1);
    k_gemm2<<<gemmBlocks, 256, SMEM_GEMM>>>(bufB, whi + D * D,     wlo + D * D,     b1b, bufA, 1, 1);
    // layer 2
    k_agg2<<<aggBlocks, 256>>>(bufA, bufB);
    k_gemm2<<<gemmBlocks, 256, SMEM_GEMM>>>(bufB, whi + 2 * D * D, wlo + 2 * D * D, b2a, bufA, 1, 1);
    k_gemm2<<<gemmBlocks, 256, SMEM_GEMM>>>(bufA, whi + 3 * D * D, wlo + 3 * D * D, b2b, bufB, 0, 0);
    // pool + classify
    k_count<<<392, 256>>>(batch);
    k_pool<<<(N_NODES + NODES_PER_BLK - 1) / NODES_PER_BLK, 128>>>((const float*)bufB, batch);
    k_final<<<N_GRAPHS, 128>>>(Wlin, blin, out);
}

// round 6
// speedup vs baseline: 1.0874x; 1.0874x over previous
#include <cuda_runtime.h>
#include <cuda_bf16.h>
#include <cstdint>

#define N_NODES  100000
#define N_PAD    100096            // 782 * 128
#define N_EDGES  1600000
#define N_GRAPHS 1000
#define D        128
#define NOUT     6
#define NT       782               // row tiles of 128
#define GRID_P   148

// ---------------- scratch (static device globals; no allocs allowed) ----------
__device__ __align__(16) __nv_bfloat16 g_hiA[N_PAD * D];
__device__ __align__(16) __nv_bfloat16 g_loA[N_PAD * D];
__device__ __align__(16) __nv_bfloat16 g_hiB[N_PAD * D];
__device__ __align__(16) __nv_bfloat16 g_loB[N_PAD * D];
__device__ __align__(16) unsigned g_packed[N_NODES * D];
__device__ __align__(16) float    g_f32[N_NODES * D];
__device__ int   g_rowptr[N_NODES + 1];
__device__ int   g_pos[N_NODES];
__device__ int   g_col[N_EDGES];
__device__ __align__(16) float g_pooled[N_GRAPHS * D];
__device__ int   g_cnt[N_GRAPHS];
__device__ int   g_flag;
__device__ __align__(16) __nv_bfloat16 g_Whi[4 * D * D];   // [k][n], element-wise split
__device__ __align__(16) __nv_bfloat16 g_Wlo[4 * D * D];

// ---------------- helpers -----------------------------------------------------
__device__ __forceinline__ long long ld_idx(const void* p, long long i, int wide) {
    return wide ? ((const long long*)p)[i] : (long long)((const int*)p)[i];
}
__device__ __forceinline__ unsigned packf(float x) {
    __nv_bfloat16 h = __float2bfloat16(x);
    __nv_bfloat16 l = __float2bfloat16(x - __bfloat162float(h));
    return (unsigned)__bfloat16_as_ushort(h) | ((unsigned)__bfloat16_as_ushort(l) << 16);
}
__device__ __forceinline__ float unpackf(unsigned p) {
    return __uint_as_float(p << 16) + __uint_as_float(p & 0xFFFF0000u);
}
__device__ __forceinline__ unsigned hi2(float a, float b) {
    __nv_bfloat16 ha = __float2bfloat16(a), hb = __float2bfloat16(b);
    return (unsigned)__bfloat16_as_ushort(ha) | ((unsigned)__bfloat16_as_ushort(hb) << 16);
}
__device__ __forceinline__ unsigned lo2(float a, float b) {
    __nv_bfloat16 ha = __float2bfloat16(a), hb = __float2bfloat16(b);
    __nv_bfloat16 la = __float2bfloat16(a - __bfloat162float(ha));
    __nv_bfloat16 lb = __float2bfloat16(b - __bfloat162float(hb));
    return (unsigned)__bfloat16_as_ushort(la) | ((unsigned)__bfloat16_as_ushort(lb) << 16);
}
__device__ __forceinline__ float2 bf2f(unsigned u) {
    __nv_bfloat162 b = *(__nv_bfloat162*)&u;
    return make_float2(__bfloat162float(b.x), __bfloat162float(b.y));
}

__global__ void k_zero_detect(const void* ei) {
    int i = blockIdx.x * blockDim.x + threadIdx.x;
    if (blockIdx.x == 0 && threadIdx.x == 0) {
        const int* p = (const int*)ei;
        int wide = 1;
        for (int k = 0; k < 64; k++)
            if (p[2 * k + 1] != 0) { wide = 0; break; }
        g_flag = wide;
    }
    int total = N_NODES + N_GRAPHS * D + N_GRAPHS;
    for (; i < total; i += gridDim.x * blockDim.x) {
        if (i < N_NODES) g_pos[i] = 0;
        else if (i < N_NODES + N_GRAPHS * D) g_pooled[i - N_NODES] = 0.0f;
        else g_cnt[i - N_NODES - N_GRAPHS * D] = 0;
    }
}

__global__ void k_hist(const void* ei) {
    int wide = g_flag;
    int e = blockIdx.x * blockDim.x + threadIdx.x;
    for (; e < N_EDGES; e += gridDim.x * blockDim.x) {
        int dst = (int)ld_idx(ei, (long long)N_EDGES + e, wide);
        atomicAdd(&g_pos[dst], 1);
    }
}

#define CHUNK 98
__global__ void k_scanall() {
    __shared__ int s[1024];
    int t = threadIdx.x;
    int beg = t * CHUNK;
    int end = beg + CHUNK; if (end > N_NODES) end = N_NODES;
    int sum = 0;
    for (int i = beg; i < end; i++) sum += g_pos[i];
    s[t] = sum;
    __syncthreads();
    for (int off = 1; off < 1024; off <<= 1) {
        int v = (t >= off) ? s[t - off] : 0;
        __syncthreads();
        s[t] += v;
        __syncthreads();
    }
    int run = s[t] - sum;
    if (t == 0) g_rowptr[0] = 0;
    for (int i = beg; i < end; i++) {
        int c = g_pos[i];
        g_pos[i] = run;
        run += c;
        g_rowptr[i + 1] = run;
    }
}

__global__ void k_fill(const void* ei) {
    int wide = g_flag;
    int e = blockIdx.x * blockDim.x + threadIdx.x;
    for (; e < N_EDGES; e += gridDim.x * blockDim.x) {
        int src = (int)ld_idx(ei, e, wide);
        int dst = (int)ld_idx(ei, (long long)N_EDGES + e, wide);
        int p = atomicAdd(&g_pos[dst], 1);
        g_col[p] = src;
    }
}

// element-wise split of 4 weight matrices (keep [k][n] layout)
__global__ void k_wprep(const float* __restrict__ Wa, const float* __restrict__ Wb,
                        const float* __restrict__ Wc, const float* __restrict__ Wd) {
    int idx = blockIdx.x * blockDim.x + threadIdx.x;
    if (idx >= 4 * D * D) return;
    int m = idx >> 14, j = idx & 16383;
    const float* W = (m == 0) ? Wa : (m == 1) ? Wb : (m == 2) ? Wc : Wd;
    float v = W[j];
    __nv_bfloat16 h = __float2bfloat16(v);
    g_Whi[idx] = h;
    g_Wlo[idx] = __float2bfloat16(v - __bfloat162float(h));
}

// agg1: f32 input -> hi/lo planes
__global__ void k_agg1(const float* __restrict__ in,
                       __nv_bfloat16* __restrict__ Chi, __nv_bfloat16* __restrict__ Clo) {
    int node = (blockIdx.x * blockDim.x + threadIdx.x) >> 5;
    int lane = threadIdx.x & 31;
    if (node >= N_NODES) return;
    const float4* in4 = (const float4*)in;
    float4 acc = in4[(long long)node * 32 + lane];
    int j = g_rowptr[node], end = g_rowptr[node + 1];
    for (; j + 2 <= end; j += 2) {
        int s0 = g_col[j], s1 = g_col[j + 1];
        float4 v0 = in4[(long long)s0 * 32 + lane];
        float4 v1 = in4[(long long)s1 * 32 + lane];
        acc.x += v0.x + v1.x; acc.y += v0.y + v1.y;
        acc.z += v0.z + v1.z; acc.w += v0.w + v1.w;
    }
    if (j < end) {
        float4 v = in4[(long long)g_col[j] * 32 + lane];
        acc.x += v.x; acc.y += v.y; acc.z += v.z; acc.w += v.w;
    }
    ((uint2*)Chi)[(long long)node * 32 + lane] = make_uint2(hi2(acc.x, acc.y), hi2(acc.z, acc.w));
    ((uint2*)Clo)[(long long)node * 32 + lane] = make_uint2(lo2(acc.x, acc.y), lo2(acc.z, acc.w));
}

// agg2: packed input -> hi/lo planes
__global__ void k_agg2(const unsigned* __restrict__ in,
                       __nv_bfloat16* __restrict__ Chi, __nv_bfloat16* __restrict__ Clo) {
    int node = (blockIdx.x * blockDim.x + threadIdx.x) >> 5;
    int lane = threadIdx.x & 31;
    if (node >= N_NODES) return;
    const uint4* in4 = (const uint4*)in;
    uint4 ps = in4[(long long)node * 32 + lane];
    float ax = unpackf(ps.x), ay = unpackf(ps.y), az = unpackf(ps.z), aw = unpackf(ps.w);
    int j = g_rowptr[node], end = g_rowptr[node + 1];
    for (; j + 2 <= end; j += 2) {
        int s0 = g_col[j], s1 = g_col[j + 1];
        uint4 p0 = in4[(long long)s0 * 32 + lane];
        uint4 p1 = in4[(long long)s1 * 32 + lane];
        ax += unpackf(p0.x) + unpackf(p1.x);
        ay += unpackf(p0.y) + unpackf(p1.y);
        az += unpackf(p0.z) + unpackf(p1.z);
        aw += unpackf(p0.w) + unpackf(p1.w);
    }
    if (j < end) {
        uint4 p = in4[(long long)g_col[j] * 32 + lane];
        ax += unpackf(p.x); ay += unpackf(p.y); az += unpackf(p.z); aw += unpackf(p.w);
    }
    ((uint2*)Chi)[(long long)node * 32 + lane] = make_uint2(hi2(ax, ay), hi2(az, aw));
    ((uint2*)Clo)[(long long)node * 32 + lane] = make_uint2(lo2(ax, ay), lo2(az, aw));
}

// ---------------- persistent tensor GEMM (bf16 3-term split) ------------------
#define LDB 136
#define WP  17408                  // one plane: 128 rows x LDB elems
#define SM_WHI 0
#define SM_WLO WP
#define SM_A0  (2 * WP)
#define SMEM_P (6 * WP * 2)        // 208896 bytes

__device__ __forceinline__ uint32_t smem_u32(const void* p) {
    uint32_t a;
    asm("{ .reg .u64 t; cvta.to.shared.u64 t, %1; cvt.u32.u64 %0, t; }" : "=r"(a) : "l"(p));
    return a;
}
__device__ __forceinline__ void ldsm4(uint32_t& r0, uint32_t& r1, uint32_t& r2, uint32_t& r3, uint32_t addr) {
    asm volatile("ldmatrix.sync.aligned.m8n8.x4.shared.b16 {%0,%1,%2,%3}, [%4];"
                 : "=r"(r0), "=r"(r1), "=r"(r2), "=r"(r3) : "r"(addr));
}
__device__ __forceinline__ void ldsm4t(uint32_t& r0, uint32_t& r1, uint32_t& r2, uint32_t& r3, uint32_t addr) {
    asm volatile("ldmatrix.sync.aligned.m8n8.x4.trans.shared.b16 {%0,%1,%2,%3}, [%4];"
                 : "=r"(r0), "=r"(r1), "=r"(r2), "=r"(r3) : "r"(addr));
}
__device__ __forceinline__ void mma_bf16(float* c, uint32_t a0, uint32_t a1, uint32_t a2, uint32_t a3,
                                         uint32_t b0, uint32_t b1) {
    asm volatile("mma.sync.aligned.m16n8k16.row.col.f32.bf16.bf16.f32 "
                 "{%0,%1,%2,%3}, {%4,%5,%6,%7}, {%8,%9}, {%0,%1,%2,%3};"
                 : "+f"(c[0]), "+f"(c[1]), "+f"(c[2]), "+f"(c[3])
                 : "r"(a0), "r"(a1), "r"(a2), "r"(a3), "r"(b0), "r"(b1));
}
__device__ __forceinline__ void stageA(uint32_t sb, int buf, int tile,
                                       const __nv_bfloat16* __restrict__ Ahi,
                                       const __nv_bfloat16* __restrict__ Alo, int t) {
    int abase = SM_A0 + buf * 2 * WP;
#pragma unroll
    for (int i = 0; i < 8; i++) {
        int lin = t + i * 256;
        int row = lin >> 4, c16 = lin & 15;
        uint32_t dst = sb + 2u * (abase + row * LDB + c16 * 8);
        long long goff = ((long long)tile * 128 + row) * 128 + c16 * 8;
        asm volatile("cp.async.cg.shared.global [%0], [%1], 16;" :: "r"(dst), "l"(Ahi + goff));
        asm volatile("cp.async.cg.shared.global [%0], [%1], 16;" :: "r"(dst + 2u * WP), "l"(Alo + goff));
    }
}

// mode: 0 = f32 out, 1 = planes out, 2 = packed out
__global__ __launch_bounds__(256, 1)
void k_gemmp(const __nv_bfloat16* __restrict__ Ahi, const __nv_bfloat16* __restrict__ Alo,
             const __nv_bfloat16* __restrict__ Whi, const __nv_bfloat16* __restrict__ Wlo,
             const float* __restrict__ bias,
             __nv_bfloat16* __restrict__ Chi, __nv_bfloat16* __restrict__ Clo,
             unsigned* __restrict__ Cpk, float* __restrict__ Cf,
             int doRelu, int mode) {
    extern __shared__ __nv_bfloat16 sm[];
    const int t = threadIdx.x;
    uint32_t sb = smem_u32(sm);

    // stage W hi/lo once (plain loads)
#pragma unroll
    for (int i = 0; i < 8; i++) {
        int lin = t + i * 256;              // 0..2047 uint4 per plane
        int row = lin >> 4, c8 = (lin & 15) * 8;
        int o = row * LDB + c8;
        *(uint4*)&sm[SM_WHI + o] = ((const uint4*)Whi)[lin];
        *(uint4*)&sm[SM_WLO + o] = ((const uint4*)Wlo)[lin];
    }

    const int w = t >> 5, lane = t & 31;
    const int mbase = (w >> 1) * 32;
    const int nbase = (w & 1) * 64;
    const int lrow = lane & 15;
    const int lcol = (lane >> 4) * 8;
    const int colb = nbase + 2 * (lane & 3);

    float2 bb[8];
#pragma unroll
    for (int nf = 0; nf < 8; nf++) bb[nf] = *(const float2*)&bias[colb + nf * 8];

    int tile = blockIdx.x;
    stageA(sb, 0, tile, Ahi, Alo, t);
    asm volatile("cp.async.commit_group;" ::: "memory");
    int buf = 0;

    for (; tile < NT; tile += GRID_P) {
        int nxt = tile + GRID_P;
        if (nxt < NT) {
            stageA(sb, buf ^ 1, nxt, Ahi, Alo, t);
            asm volatile("cp.async.commit_group;" ::: "memory");
            asm volatile("cp.async.wait_group 1;" ::: "memory");
        } else {
            asm volatile("cp.async.wait_group 0;" ::: "memory");
        }
        __syncthreads();

        float acc[2][8][4];
#pragma unroll
        for (int mi = 0; mi < 2; mi++)
#pragma unroll
            for (int nf = 0; nf < 8; nf++)
#pragma unroll
                for (int r = 0; r < 4; r++) acc[mi][nf][r] = 0.f;

        const int aHi = SM_A0 + buf * 2 * WP;
        const int aLo = aHi + WP;
        const int aOffs[3] = {aHi, aHi, aLo};
        const int wOffs[3] = {SM_WHI, SM_WLO, SM_WHI};

#pragma unroll
        for (int pass = 0; pass < 3; pass++) {
            const int aOff = aOffs[pass];
            const int wOff = wOffs[pass];
#pragma unroll
            for (int kk = 0; kk < 8; kk++) {
                const int k0 = kk * 16;
                uint32_t a[2][4];
                uint32_t addrA = sb + 2u * (aOff + (mbase + lrow) * LDB + k0 + lcol);
                ldsm4(a[0][0], a[0][1], a[0][2], a[0][3], addrA);
                ldsm4(a[1][0], a[1][1], a[1][2], a[1][3], addrA + 2u * 16 * LDB);
                uint32_t bfr[4][4];
#pragma unroll
                for (int ni = 0; ni < 4; ni++)
                    ldsm4t(bfr[ni][0], bfr[ni][1], bfr[ni][2], bfr[ni][3],
                           sb + 2u * (wOff + (k0 + lrow) * LDB + nbase + ni * 16 + lcol));
#pragma unroll
                for (int mi = 0; mi < 2; mi++)
#pragma unroll
                    for (int ni = 0; ni < 4; ni++) {
                        mma_bf16(acc[mi][2 * ni],     a[mi][0], a[mi][1], a[mi][2], a[mi][3], bfr[ni][0], bfr[ni][1]);
                        mma_bf16(acc[mi][2 * ni + 1], a[mi][0], a[mi][1], a[mi][2], a[mi][3], bfr[ni][2], bfr[ni][3]);
                    }
            }
        }

        // epilogue
        long long rowBase = (long long)tile * 128 + mbase + (lane >> 2);
#pragma unroll
        for (int mi = 0; mi < 2; mi++) {
#pragma unroll
            for (int half = 0; half < 2; half++) {
                long long rr = rowBase + mi * 16 + half * 8;
                if (rr >= N_NODES) continue;
#pragma unroll
                for (int nf = 0; nf < 8; nf++) {
                    float vx = acc[mi][nf][half * 2 + 0] + bb[nf].x;
                    float vy = acc[mi][nf][half * 2 + 1] + bb[nf].y;
                    if (doRelu) { vx = fmaxf(vx, 0.f); vy = fmaxf(vy, 0.f); }
                    long long oidx = rr * 128 + colb + nf * 8;
                    if (mode == 1) {
                        *(unsigned*)&Chi[oidx] = hi2(vx, vy);
                        *(unsigned*)&Clo[oidx] = lo2(vx, vy);
                    } else if (mode == 2) {
                        *(uint2*)&Cpk[oidx] = make_uint2(packf(vx), packf(vy));
                    } else {
                        *(float2*)&Cf[oidx] = make_float2(vx, vy);
                    }
                }
            }
        }
        __syncthreads();
        buf ^= 1;
    }
}

// per-graph counts
__global__ void k_count(const void* batch) {
    int wide = g_flag;
    int n = blockIdx.x * blockDim.x + threadIdx.x;
    for (; n < N_NODES; n += gridDim.x * blockDim.x) {
        int g = (int)ld_idx(batch, n, wide);
        atomicAdd(&g_cnt[g], 1);
    }
}

#define NODES_PER_BLK 512
__global__ void k_pool(const float* __restrict__ h, const void* batch) {
    int wide = g_flag;
    int f = threadIdx.x;
    int base = blockIdx.x * NODES_PER_BLK;
    int end = base + NODES_PER_BLK;
    if (end > N_NODES) end = N_NODES;
    float run = 0.0f;
    int cur = -1;
    for (int n = base; n < end; n++) {
        int g = (int)ld_idx(batch, n, wide);
        if (g != cur) {
            if (cur >= 0) atomicAdd(&g_pooled[cur * D + f], run);
            cur = g;
            run = 0.0f;
        }
        run += h[(long long)n * D + f];
    }
    if (cur >= 0) atomicAdd(&g_pooled[cur * D + f], run);
}

__global__ void k_final(const float* __restrict__ Wlin, const float* __restrict__ blin,
                        float* __restrict__ out) {
    int g = blockIdx.x;
    int k = threadIdx.x;
    float c = (float)g_cnt[g];
    if (c < 1.0f) c = 1.0f;
    float v = g_pooled[g * D + k] / c;
    __shared__ float red[128];
    for (int j = 0; j < NOUT; j++) {
        red[k] = v * Wlin[k * NOUT + j];
        __syncthreads();
        for (int s = 64; s > 0; s >>= 1) {
            if (k < s) red[k] += red[k + s];
            __syncthreads();
        }
        if (k == 0) out[g * NOUT + j] = red[0] + blin[j];
        __syncthreads();
    }
}

// ---------------- launch ------------------------------------------------------
extern "C" void kernel_launch(void* const* d_in, const int* in_sizes, int n_in,
                              void* d_out, int out_size) {
    const float* x    = (const float*)d_in[0];
    const void*  ei   = d_in[1];
    const void*  batch= d_in[2];
    const float* W1a  = (const float*)d_in[3];
    const float* b1a  = (const float*)d_in[4];
    const float* W1b  = (const float*)d_in[5];
    const float* b1b  = (const float*)d_in[6];
    const float* W2a  = (const float*)d_in[7];
    const float* b2a  = (const float*)d_in[8];
    const float* W2b  = (const float*)d_in[9];
    const float* b2b  = (const float*)d_in[10];
    const float* Wlin = (const float*)d_in[11];
    const float* blin = (const float*)d_in[12];
    float* out = (float*)d_out;

    __nv_bfloat16 *hiA, *loA, *hiB, *loB, *whi, *wlo;
    unsigned* pk;
    float* f32;
    cudaGetSymbolAddress((void**)&hiA, g_hiA);
    cudaGetSymbolAddress((void**)&loA, g_loA);
    cudaGetSymbolAddress((void**)&hiB, g_hiB);
    cudaGetSymbolAddress((void**)&loB, g_loB);
    cudaGetSymbolAddress((void**)&pk,  g_packed);
    cudaGetSymbolAddress((void**)&f32, g_f32);
    cudaGetSymbolAddress((void**)&whi, g_Whi);
    cudaGetSymbolAddress((void**)&wlo, g_Wlo);

    cudaFuncSetAttribute(k_gemmp, cudaFuncAttributeMaxDynamicSharedMemorySize, SMEM_P);

    const int aggBlocks = (N_NODES * 32 + 255) / 256;

    k_zero_detect<<<448, 512>>>(ei);
    k_hist<<<6250, 256>>>(ei);
    k_scanall<<<1, 1024>>>();
    k_fill<<<6250, 256>>>(ei);
    k_wprep<<<(4 * D * D + 255) / 256, 256>>>(W1a, W1b, W2a, W2b);

    // layer 1
    k_agg1<<<aggBlocks, 256>>>(x, hiA, loA);
    k_gemmp<<<GRID_P, 256, SMEM_P>>>(hiA, loA, whi,             wlo,             b1a, hiB, loB, pk, f32, 1, 1);
    k_gemmp<<<GRID_P, 256, SMEM_P>>>(hiB, loB, whi + D * D,     wlo + D * D,     b1b, hiA, loA, pk, f32, 1, 2);
    // layer 2
    k_agg2<<<aggBlocks, 256>>>(pk, hiA, loA);
    k_gemmp<<<GRID_P, 256, SMEM_P>>>(hiA, loA, whi + 2 * D * D, wlo + 2 * D * D, b2a, hiB, loB, pk, f32, 1, 1);
    k_gemmp<<<GRID_P, 256, SMEM_P>>>(hiB, loB, whi + 3 * D * D, wlo + 3 * D * D, b2b, hiA, loA, pk, f32, 0, 0);
    // pool + classify
    k_count<<<392, 256>>>(batch);
    k_pool<<<(N_NODES + NODES_PER_BLK - 1) / NODES_PER_BLK, 128>>>(f32, batch);
    k_final<<<N_GRAPHS, 128>>>(Wlin, blin, out);
}

// round 7
// speedup vs baseline: 1.3809x; 1.2700x over previous
#include <cuda_runtime.h>
#include <cuda_fp16.h>
#include <cstdint>

#define N_NODES  100000
#define N_EDGES  1600000
#define N_GRAPHS 1000
#define D        128
#define NOUT     6
#define TILE_M   64
#define NT       1563              // ceil(100000/64)

// ---------------- scratch (static device globals; no allocs allowed) ----------
__device__ __align__(16) __half g_fA[N_NODES * D];
__device__ __align__(16) __half g_fB[N_NODES * D];
__device__ __align__(16) float  g_f32[N_NODES * D];
__device__ int   g_rowptr[N_NODES + 1];
__device__ int   g_pos[N_NODES];
__device__ int   g_col[N_EDGES];
__device__ __align__(16) float g_pooled[N_GRAPHS * D];
__device__ int   g_cnt[N_GRAPHS];
__device__ int   g_flag;
__device__ __align__(16) __half g_Whi[4 * D * D];   // [k][n] row-major, fp16 hi
__device__ __align__(16) __half g_Wlo[4 * D * D];   // fp16 lo residual

// ---------------- helpers -----------------------------------------------------
__device__ __forceinline__ long long ld_idx(const void* p, long long i, int wide) {
    return wide ? ((const long long*)p)[i] : (long long)((const int*)p)[i];
}

// 1: zero scratch + dtype detect
__global__ void k_zero_detect(const void* ei) {
    int i = blockIdx.x * blockDim.x + threadIdx.x;
    if (blockIdx.x == 0 && threadIdx.x == 0) {
        const int* p = (const int*)ei;
        int wide = 1;
        for (int k = 0; k < 64; k++)
            if (p[2 * k + 1] != 0) { wide = 0; break; }
        g_flag = wide;
    }
    int total = N_NODES + N_GRAPHS * D + N_GRAPHS;
    for (; i < total; i += gridDim.x * blockDim.x) {
        if (i < N_NODES) g_pos[i] = 0;
        else if (i < N_NODES + N_GRAPHS * D) g_pooled[i - N_NODES] = 0.0f;
        else g_cnt[i - N_NODES - N_GRAPHS * D] = 0;
    }
}

// 2: split 4 weight matrices into fp16 hi/lo, keep [k][n] layout
__global__ void k_wprep(const float* __restrict__ Wa, const float* __restrict__ Wb,
                        const float* __restrict__ Wc, const float* __restrict__ Wd) {
    int idx = blockIdx.x * blockDim.x + threadIdx.x;
    if (idx >= 4 * D * D) return;
    int m = idx >> 14, j = idx & 16383;
    const float* W = (m == 0) ? Wa : (m == 1) ? Wb : (m == 2) ? Wc : Wd;
    float v = W[j];
    __half h = __float2half_rn(v);
    g_Whi[idx] = h;
    g_Wlo[idx] = __float2half_rn(v - __half2float(h));
}

// 3: x f32 -> fp16
__global__ void k_convx(const float* __restrict__ x, __half* __restrict__ out) {
    int i = blockIdx.x * blockDim.x + threadIdx.x;   // one float4 -> 2 half2
    if (i >= N_NODES * 32) return;
    float4 v = ((const float4*)x)[i];
    __half2 a = __floats2half2_rn(v.x, v.y);
    __half2 b = __floats2half2_rn(v.z, v.w);
    ((uint2*)out)[i] = make_uint2(*(unsigned*)&a, *(unsigned*)&b);
}

// ---------------- fp16 2-pass tensor GEMM -------------------------------------
// C[64 x 128] = A[64 x 128] @ (Whi + Wlo)  (+bias, relu, out fp16 or f32)
#define LDB    136
#define SM_WHI 0
#define SM_WLO 17408
#define SM_A   34816
#define SMEM_G ((34816 + 8704) * 2)     // 87040 bytes

__device__ __forceinline__ uint32_t smem_u32(const void* p) {
    uint32_t a;
    asm("{ .reg .u64 t; cvta.to.shared.u64 t, %1; cvt.u32.u64 %0, t; }" : "=r"(a) : "l"(p));
    return a;
}
__device__ __forceinline__ void ldsm4(uint32_t& r0, uint32_t& r1, uint32_t& r2, uint32_t& r3, uint32_t addr) {
    asm volatile("ldmatrix.sync.aligned.m8n8.x4.shared.b16 {%0,%1,%2,%3}, [%4];"
                 : "=r"(r0), "=r"(r1), "=r"(r2), "=r"(r3) : "r"(addr));
}
__device__ __forceinline__ void ldsm4t(uint32_t& r0, uint32_t& r1, uint32_t& r2, uint32_t& r3, uint32_t addr) {
    asm volatile("ldmatrix.sync.aligned.m8n8.x4.trans.shared.b16 {%0,%1,%2,%3}, [%4];"
                 : "=r"(r0), "=r"(r1), "=r"(r2), "=r"(r3) : "r"(addr));
}
__device__ __forceinline__ void mma_f16(float* c, uint32_t a0, uint32_t a1, uint32_t a2, uint32_t a3,
                                        uint32_t b0, uint32_t b1) {
    asm volatile("mma.sync.aligned.m16n8k16.row.col.f32.f16.f16.f32 "
                 "{%0,%1,%2,%3}, {%4,%5,%6,%7}, {%8,%9}, {%0,%1,%2,%3};"
                 : "+f"(c[0]), "+f"(c[1]), "+f"(c[2]), "+f"(c[3])
                 : "r"(a0), "r"(a1), "r"(a2), "r"(a3), "r"(b0), "r"(b1));
}
__device__ __forceinline__ void cpa16(uint32_t dst, const void* src, int srcsize) {
    asm volatile("cp.async.cg.shared.global [%0], [%1], 16, %2;"
                 :: "r"(dst), "l"(src), "r"(srcsize));
}

// mode: 0 = f32 out, 1 = fp16 out ; hasBias/doRelu flags
__global__ __launch_bounds__(256, 2)
void k_gemm(const __half* __restrict__ Ain,
            const __half* __restrict__ Whi, const __half* __restrict__ Wlo,
            const float* __restrict__ bias,
            __half* __restrict__ Ch, float* __restrict__ Cf,
            int doRelu, int mode) {
    extern __shared__ __half sm[];
    const int t = threadIdx.x;
    uint32_t sb = smem_u32(sm);
    const long long blockRow = (long long)blockIdx.x * TILE_M;

    // stage W hi/lo (2048 x 16B each) + A tile (1024 x 16B) via cp.async
#pragma unroll
    for (int i = 0; i < 8; i++) {
        int lin = t + i * 256;              // 0..2047
        int row = lin >> 4, c = (lin & 15) * 8;
        uint32_t dst = sb + 2u * (row * LDB + c);
        cpa16(dst + 2u * SM_WHI, Whi + row * 128 + c, 16);
        cpa16(dst + 2u * SM_WLO, Wlo + row * 128 + c, 16);
    }
#pragma unroll
    for (int i = 0; i < 4; i++) {
        int lin = t + i * 256;              // 0..1023
        int row = lin >> 4, c = (lin & 15) * 8;
        long long gr = blockRow + row;
        int ok = (gr < N_NODES) ? 16 : 0;
        long long src = (gr < N_NODES) ? gr : 0;
        cpa16(sb + 2u * (SM_A + row * LDB + c), Ain + src * 128 + c, ok);
    }
    asm volatile("cp.async.commit_group;" ::: "memory");
    asm volatile("cp.async.wait_group 0;" ::: "memory");
    __syncthreads();

    const int w = t >> 5, lane = t & 31;
    const int mbase = (w >> 1) * 16;        // 4 m-warps x 16 rows
    const int nbase = (w & 1) * 64;         // 2 n-warps x 64 cols
    const int lrow = lane & 15;
    const int lcol = (lane >> 4) * 8;

    float acc[8][4];
#pragma unroll
    for (int nf = 0; nf < 8; nf++)
#pragma unroll
        for (int r = 0; r < 4; r++) acc[nf][r] = 0.f;

#pragma unroll
    for (int pass = 0; pass < 2; pass++) {
        const int wOff = pass ? SM_WLO : SM_WHI;
#pragma unroll
        for (int kk = 0; kk < 8; kk++) {
            const int k0 = kk * 16;
            uint32_t a0, a1, a2, a3;
            ldsm4(a0, a1, a2, a3, sb + 2u * (SM_A + (mbase + lrow) * LDB + k0 + lcol));
            uint32_t b[4][4];
#pragma unroll
            for (int ni = 0; ni < 4; ni++)
                ldsm4t(b[ni][0], b[ni][1], b[ni][2], b[ni][3],
                       sb + 2u * (wOff + (k0 + lrow) * LDB + nbase + ni * 16 + lcol));
#pragma unroll
            for (int ni = 0; ni < 4; ni++) {
                mma_f16(acc[2 * ni],     a0, a1, a2, a3, b[ni][0], b[ni][1]);
                mma_f16(acc[2 * ni + 1], a0, a1, a2, a3, b[ni][2], b[ni][3]);
            }
        }
    }

    // epilogue
    const int colb = nbase + 2 * (lane & 3);
    const long long r0 = blockRow + mbase + (lane >> 2);
#pragma unroll
    for (int nf = 0; nf < 8; nf++) {
        float bx = 0.f, by = 0.f;
        if (bias) { float2 bb = *(const float2*)&bias[colb + nf * 8]; bx = bb.x; by = bb.y; }
#pragma unroll
        for (int half = 0; half < 2; half++) {
            long long rr = r0 + half * 8;
            if (rr >= N_NODES) continue;
            float vx = acc[nf][half * 2 + 0] + bx;
            float vy = acc[nf][half * 2 + 1] + by;
            if (doRelu) { vx = fmaxf(vx, 0.f); vy = fmaxf(vy, 0.f); }
            long long oidx = rr * 128 + colb + nf * 8;
            if (mode == 1) {
                __half2 h = __floats2half2_rn(vx, vy);
                *(unsigned*)&Ch[oidx] = *(unsigned*)&h;
            } else {
                *(float2*)&Cf[oidx] = make_float2(vx, vy);
            }
        }
    }
}

// CSR build
__global__ void k_hist(const void* ei) {
    int wide = g_flag;
    int e = blockIdx.x * blockDim.x + threadIdx.x;
    for (; e < N_EDGES; e += gridDim.x * blockDim.x) {
        int dst = (int)ld_idx(ei, (long long)N_EDGES + e, wide);
        atomicAdd(&g_pos[dst], 1);
    }
}

#define CHUNK 98
__global__ void k_scanall() {
    __shared__ int s[1024];
    int t = threadIdx.x;
    int beg = t * CHUNK;
    int end = beg + CHUNK; if (end > N_NODES) end = N_NODES;
    int sum = 0;
    for (int i = beg; i < end; i++) sum += g_pos[i];
    s[t] = sum;
    __syncthreads();
    for (int off = 1; off < 1024; off <<= 1) {
        int v = (t >= off) ? s[t - off] : 0;
        __syncthreads();
        s[t] += v;
        __syncthreads();
    }
    int run = s[t] - sum;
    if (t == 0) g_rowptr[0] = 0;
    for (int i = beg; i < end; i++) {
        int c = g_pos[i];
        g_pos[i] = run;
        run += c;
        g_rowptr[i + 1] = run;
    }
}

__global__ void k_fill(const void* ei) {
    int wide = g_flag;
    int e = blockIdx.x * blockDim.x + threadIdx.x;
    for (; e < N_EDGES; e += gridDim.x * blockDim.x) {
        int src = (int)ld_idx(ei, e, wide);
        int dst = (int)ld_idx(ei, (long long)N_EDGES + e, wide);
        int p = atomicAdd(&g_pos[dst], 1);
        g_col[p] = src;
    }
}

// agg + bias + relu: out[n] = relu(in[n] + sum_neigh in[j] + bias), fp16 io
__global__ void k_aggbr(const __half* __restrict__ in, __half* __restrict__ out,
                        const float* __restrict__ bias) {
    int node = (blockIdx.x * blockDim.x + threadIdx.x) >> 5;
    int lane = threadIdx.x & 31;
    if (node >= N_NODES) return;
    const uint2* in2 = (const uint2*)in;
    uint2 s = in2[(long long)node * 32 + lane];
    float2 p0 = __half22float2(*(__half2*)&s.x);
    float2 p1 = __half22float2(*(__half2*)&s.y);
    float a0 = p0.x, a1 = p0.y, a2 = p1.x, a3 = p1.y;
    int j = g_rowptr[node], end = g_rowptr[node + 1];
    for (; j + 2 <= end; j += 2) {
        uint2 v0 = in2[(long long)g_col[j] * 32 + lane];
        uint2 v1 = in2[(long long)g_col[j + 1] * 32 + lane];
        float2 q0 = __half22float2(*(__half2*)&v0.x);
        float2 q1 = __half22float2(*(__half2*)&v0.y);
        float2 r0 = __half22float2(*(__half2*)&v1.x);
        float2 r1 = __half22float2(*(__half2*)&v1.y);
        a0 += q0.x + r0.x; a1 += q0.y + r0.y;
        a2 += q1.x + r1.x; a3 += q1.y + r1.y;
    }
    if (j < end) {
        uint2 v = in2[(long long)g_col[j] * 32 + lane];
        float2 q0 = __half22float2(*(__half2*)&v.x);
        float2 q1 = __half22float2(*(__half2*)&v.y);
        a0 += q0.x; a1 += q0.y; a2 += q1.x; a3 += q1.y;
    }
    float4 b = *(const float4*)&bias[lane * 4];
    a0 = fmaxf(a0 + b.x, 0.f);
    a1 = fmaxf(a1 + b.y, 0.f);
    a2 = fmaxf(a2 + b.z, 0.f);
    a3 = fmaxf(a3 + b.w, 0.f);
    __half2 h0 = __floats2half2_rn(a0, a1);
    __half2 h1 = __floats2half2_rn(a2, a3);
    ((uint2*)out)[(long long)node * 32 + lane] = make_uint2(*(unsigned*)&h0, *(unsigned*)&h1);
}

// pool (+ per-graph counts fused): batch sorted -> register run accumulation
#define NODES_PER_BLK 512
__global__ void k_pool(const float* __restrict__ h, const void* batch) {
    int wide = g_flag;
    int f = threadIdx.x;
    int base = blockIdx.x * NODES_PER_BLK;
    int end = base + NODES_PER_BLK;
    if (end > N_NODES) end = N_NODES;
    float run = 0.0f;
    int cur = -1, nrun = 0;
    for (int n = base; n < end; n++) {
        int g = (int)ld_idx(batch, n, wide);
        if (g != cur) {
            if (cur >= 0) {
                atomicAdd(&g_pooled[cur * D + f], run);
                if (f == 0) atomicAdd(&g_cnt[cur], nrun);
            }
            cur = g; run = 0.0f; nrun = 0;
        }
        run += h[(long long)n * D + f];
        nrun++;
    }
    if (cur >= 0) {
        atomicAdd(&g_pooled[cur * D + f], run);
        if (f == 0) atomicAdd(&g_cnt[cur], nrun);
    }
}

__global__ void k_final(const float* __restrict__ Wlin, const float* __restrict__ blin,
                        float* __restrict__ out) {
    int g = blockIdx.x;
    int k = threadIdx.x;
    float c = (float)g_cnt[g];
    if (c < 1.0f) c = 1.0f;
    float v = g_pooled[g * D + k] / c;
    __shared__ float red[128];
    for (int j = 0; j < NOUT; j++) {
        red[k] = v * Wlin[k * NOUT + j];
        __syncthreads();
        for (int s = 64; s > 0; s >>= 1) {
            if (k < s) red[k] += red[k + s];
            __syncthreads();
        }
        if (k == 0) out[g * NOUT + j] = red[0] + blin[j];
        __syncthreads();
    }
}

// ---------------- launch ------------------------------------------------------
extern "C" void kernel_launch(void* const* d_in, const int* in_sizes, int n_in,
                              void* d_out, int out_size) {
    const float* x    = (const float*)d_in[0];
    const void*  ei   = d_in[1];
    const void*  batch= d_in[2];
    const float* b1a  = (const float*)d_in[4];
    const float* b1b  = (const float*)d_in[6];
    const float* b2a  = (const float*)d_in[8];
    const float* b2b  = (const float*)d_in[10];
    const float* Wlin = (const float*)d_in[11];
    const float* blin = (const float*)d_in[12];
    float* out = (float*)d_out;

    __half *fA, *fB, *whi, *wlo;
    float* f32;
    cudaGetSymbolAddress((void**)&fA,  g_fA);
    cudaGetSymbolAddress((void**)&fB,  g_fB);
    cudaGetSymbolAddress((void**)&f32, g_f32);
    cudaGetSymbolAddress((void**)&whi, g_Whi);
    cudaGetSymbolAddress((void**)&wlo, g_Wlo);

    cudaFuncSetAttribute(k_gemm, cudaFuncAttributeMaxDynamicSharedMemorySize, SMEM_G);

    const int aggBlocks = (N_NODES * 32 + 255) / 256;

    // layer1 rewrite via linearity: u = x@W1a ; v = relu(u + agg(u) + b1a)
    k_zero_detect<<<448, 512>>>(ei);
    k_wprep<<<(4 * D * D + 255) / 256, 256>>>((const float*)d_in[3], (const float*)d_in[5],
                                              (const float*)d_in[7], (const float*)d_in[9]);
    k_convx<<<(N_NODES * 32 + 255) / 256, 256>>>(x, fA);
    k_gemm<<<NT, 256, SMEM_G>>>(fA, whi,             wlo,             nullptr, fB, f32, 0, 1); // u
    k_hist<<<6250, 256>>>(ei);
    k_scanall<<<1, 1024>>>();
    k_fill<<<6250, 256>>>(ei);
    k_aggbr<<<aggBlocks, 256>>>(fB, fA, b1a);                                                  // v
    k_gemm<<<NT, 256, SMEM_G>>>(fA, whi + D * D,     wlo + D * D,     b1b, fB, f32, 1, 1);     // h1
    // layer2: p = h1@W2a ; q = relu(p + agg(p) + b2a) ; r = q@W2b + b2b
    k_gemm<<<NT, 256, SMEM_G>>>(fB, whi + 2 * D * D, wlo + 2 * D * D, nullptr, fA, f32, 0, 1); // p
    k_aggbr<<<aggBlocks, 256>>>(fA, fB, b2a);                                                  // q
    k_gemm<<<NT, 256, SMEM_G>>>(fB, whi + 3 * D * D, wlo + 3 * D * D, b2b, fA, f32, 0, 0);     // r -> f32
    // pool + classify
    k_pool<<<(N_NODES + NODES_PER_BLK - 1) / NODES_PER_BLK, 128>>>(f32, batch);
    k_final<<<N_GRAPHS, 128>>>(Wlin, blin, out);
}

// round 8
// speedup vs baseline: 2.9109x; 2.1079x over previous
#include <cuda_runtime.h>
#include <cuda_fp16.h>
#include <cstdint>

#define N_NODES  100000
#define N_EDGES  1600000
#define N_GRAPHS 1000
#define D        128
#define NOUT     6
#define TILE_M   64
#define NT       1563              // ceil(100000/64)
#define NB_SCAN  ((N_NODES + 1023) / 1024)   // 98

// ---------------- scratch (static device globals; no allocs allowed) ----------
__device__ __align__(16) __half g_fA[N_NODES * D];
__device__ __align__(16) __half g_fB[N_NODES * D];
__device__ __align__(16) float  g_f32[N_NODES * D];
__device__ int   g_rowptr[N_NODES + 1];
__device__ int   g_pos[N_NODES];
__device__ int   g_col[N_EDGES];
__device__ int   g_bsum[NB_SCAN];
__device__ int   g_bscan[NB_SCAN];
__device__ __align__(16) float g_pooled[N_GRAPHS * D];
__device__ int   g_cnt[N_GRAPHS];
__device__ int   g_flag;
__device__ __align__(16) __half g_W[4 * D * D];   // [k][n] row-major fp16

// ---------------- helpers -----------------------------------------------------
__device__ __forceinline__ long long ld_idx(const void* p, long long i, int wide) {
    return wide ? ((const long long*)p)[i] : (long long)((const int*)p)[i];
}

// 1: zero scratch + dtype detect
__global__ void k_zero_detect(const void* ei) {
    int i = blockIdx.x * blockDim.x + threadIdx.x;
    if (blockIdx.x == 0 && threadIdx.x == 0) {
        const int* p = (const int*)ei;
        int wide = 1;
        for (int k = 0; k < 64; k++)
            if (p[2 * k + 1] != 0) { wide = 0; break; }
        g_flag = wide;
    }
    int total = N_NODES + N_GRAPHS * D + N_GRAPHS;
    for (; i < total; i += gridDim.x * blockDim.x) {
        if (i < N_NODES) g_pos[i] = 0;
        else if (i < N_NODES + N_GRAPHS * D) g_pooled[i - N_NODES] = 0.0f;
        else g_cnt[i - N_NODES - N_GRAPHS * D] = 0;
    }
}

// 2: weights -> fp16, keep [k][n] layout
__global__ void k_wprep(const float* __restrict__ Wa, const float* __restrict__ Wb,
                        const float* __restrict__ Wc, const float* __restrict__ Wd) {
    int idx = blockIdx.x * blockDim.x + threadIdx.x;
    if (idx >= 4 * D * D) return;
    int m = idx >> 14, j = idx & 16383;
    const float* W = (m == 0) ? Wa : (m == 1) ? Wb : (m == 2) ? Wc : Wd;
    g_W[idx] = __float2half_rn(W[j]);
}

// 3: x f32 -> fp16
__global__ void k_convx(const float* __restrict__ x, __half* __restrict__ out) {
    int i = blockIdx.x * blockDim.x + threadIdx.x;
    if (i >= N_NODES * 32) return;
    float4 v = ((const float4*)x)[i];
    __half2 a = __floats2half2_rn(v.x, v.y);
    __half2 b = __floats2half2_rn(v.z, v.w);
    ((uint2*)out)[i] = make_uint2(*(unsigned*)&a, *(unsigned*)&b);
}

// CSR build
__global__ void k_hist(const void* ei) {
    int wide = g_flag;
    int e = blockIdx.x * blockDim.x + threadIdx.x;
    for (; e < N_EDGES; e += gridDim.x * blockDim.x) {
        int dst = (int)ld_idx(ei, (long long)N_EDGES + e, wide);
        atomicAdd(&g_pos[dst], 1);
    }
}

__global__ void k_scan1() {
    __shared__ int s[1024];
    int t = threadIdx.x;
    int i = blockIdx.x * 1024 + t;
    int v = (i < N_NODES) ? g_pos[i] : 0;
    s[t] = v;
    __syncthreads();
    for (int off = 1; off < 1024; off <<= 1) {
        int x = (t >= off) ? s[t - off] : 0;
        __syncthreads();
        s[t] += x;
        __syncthreads();
    }
    if (i < N_NODES) g_rowptr[i + 1] = s[t];
    if (t == 1023) g_bsum[blockIdx.x] = s[1023];
}

__global__ void k_scan2() {
    int run = 0;
    for (int b = 0; b < NB_SCAN; b++) {
        int v = g_bsum[b];
        g_bscan[b] = run;
        run += v;
    }
}

// finalize rowptr AND write fill cursors (g_pos[i] = rowptr[i])
__global__ void k_scan3() {
    int t = threadIdx.x;
    int i = blockIdx.x * 1024 + t;
    if (i < N_NODES) {
        int v = g_rowptr[i + 1] + g_bscan[blockIdx.x];
        g_rowptr[i + 1] = v;
        if (i + 1 < N_NODES) g_pos[i + 1] = v;
    }
    if (i == 0) { g_rowptr[0] = 0; g_pos[0] = 0; }
}

__global__ void k_fill(const void* ei) {
    int wide = g_flag;
    int e = blockIdx.x * blockDim.x + threadIdx.x;
    for (; e < N_EDGES; e += gridDim.x * blockDim.x) {
        int src = (int)ld_idx(ei, e, wide);
        int dst = (int)ld_idx(ei, (long long)N_EDGES + e, wide);
        int p = atomicAdd(&g_pos[dst], 1);
        g_col[p] = src;
    }
}

// ---------------- fp16 single-pass tensor GEMM --------------------------------
// C[64 x 128] = A[64 x 128] @ W  (+bias, relu; out fp16 or f32)
#define LDB    136
#define SM_W   0
#define SM_A   17408
#define SMEM_G ((17408 + 8704) * 2)     // 52224 bytes

__device__ __forceinline__ uint32_t smem_u32(const void* p) {
    uint32_t a;
    asm("{ .reg .u64 t; cvta.to.shared.u64 t, %1; cvt.u32.u64 %0, t; }" : "=r"(a) : "l"(p));
    return a;
}
__device__ __forceinline__ void ldsm4(uint32_t& r0, uint32_t& r1, uint32_t& r2, uint32_t& r3, uint32_t addr) {
    asm volatile("ldmatrix.sync.aligned.m8n8.x4.shared.b16 {%0,%1,%2,%3}, [%4];"
                 : "=r"(r0), "=r"(r1), "=r"(r2), "=r"(r3) : "r"(addr));
}
__device__ __forceinline__ void ldsm4t(uint32_t& r0, uint32_t& r1, uint32_t& r2, uint32_t& r3, uint32_t addr) {
    asm volatile("ldmatrix.sync.aligned.m8n8.x4.trans.shared.b16 {%0,%1,%2,%3}, [%4];"
                 : "=r"(r0), "=r"(r1), "=r"(r2), "=r"(r3) : "r"(addr));
}
__device__ __forceinline__ void mma_f16(float* c, uint32_t a0, uint32_t a1, uint32_t a2, uint32_t a3,
                                        uint32_t b0, uint32_t b1) {
    asm volatile("mma.sync.aligned.m16n8k16.row.col.f32.f16.f16.f32 "
                 "{%0,%1,%2,%3}, {%4,%5,%6,%7}, {%8,%9}, {%0,%1,%2,%3};"
                 : "+f"(c[0]), "+f"(c[1]), "+f"(c[2]), "+f"(c[3])
                 : "r"(a0), "r"(a1), "r"(a2), "r"(a3), "r"(b0), "r"(b1));
}
__device__ __forceinline__ void cpa16(uint32_t dst, const void* src, int srcsize) {
    asm volatile("cp.async.cg.shared.global [%0], [%1], 16, %2;"
                 :: "r"(dst), "l"(src), "r"(srcsize));
}

// mode: 0 = f32 out, 1 = fp16 out
__global__ __launch_bounds__(256, 3)
void k_gemm(const __half* __restrict__ Ain, const __half* __restrict__ W,
            const float* __restrict__ bias,
            __half* __restrict__ Ch, float* __restrict__ Cf,
            int doRelu, int mode) {
    extern __shared__ __half sm[];
    const int t = threadIdx.x;
    uint32_t sb = smem_u32(sm);
    const long long blockRow = (long long)blockIdx.x * TILE_M;

    // stage W (2048 x 16B) + A tile (1024 x 16B) via cp.async
#pragma unroll
    for (int i = 0; i < 8; i++) {
        int lin = t + i * 256;              // 0..2047
        int row = lin >> 4, c = (lin & 15) * 8;
        cpa16(sb + 2u * (SM_W + row * LDB + c), W + row * 128 + c, 16);
    }
#pragma unroll
    for (int i = 0; i < 4; i++) {
        int lin = t + i * 256;              // 0..1023
        int row = lin >> 4, c = (lin & 15) * 8;
        long long gr = blockRow + row;
        int ok = (gr < N_NODES) ? 16 : 0;
        long long src = (gr < N_NODES) ? gr : 0;
        cpa16(sb + 2u * (SM_A + row * LDB + c), Ain + src * 128 + c, ok);
    }
    asm volatile("cp.async.commit_group;" ::: "memory");
    asm volatile("cp.async.wait_group 0;" ::: "memory");
    __syncthreads();

    const int w = t >> 5, lane = t & 31;
    const int mbase = (w >> 1) * 16;        // 4 m-warps x 16 rows
    const int nbase = (w & 1) * 64;         // 2 n-warps x 64 cols
    const int lrow = lane & 15;
    const int lcol = (lane >> 4) * 8;

    float acc[8][4];
#pragma unroll
    for (int nf = 0; nf < 8; nf++)
#pragma unroll
        for (int r = 0; r < 4; r++) acc[nf][r] = 0.f;

#pragma unroll
    for (int kk = 0; kk < 8; kk++) {
        const int k0 = kk * 16;
        uint32_t a0, a1, a2, a3;
        ldsm4(a0, a1, a2, a3, sb + 2u * (SM_A + (mbase + lrow) * LDB + k0 + lcol));
        uint32_t b[4][4];
#pragma unroll
        for (int ni = 0; ni < 4; ni++)
            ldsm4t(b[ni][0], b[ni][1], b[ni][2], b[ni][3],
                   sb + 2u * (SM_W + (k0 + lrow) * LDB + nbase + ni * 16 + lcol));
#pragma unroll
        for (int ni = 0; ni < 4; ni++) {
            mma_f16(acc[2 * ni],     a0, a1, a2, a3, b[ni][0], b[ni][1]);
            mma_f16(acc[2 * ni + 1], a0, a1, a2, a3, b[ni][2], b[ni][3]);
        }
    }

    // epilogue
    const int colb = nbase + 2 * (lane & 3);
    const long long r0 = blockRow + mbase + (lane >> 2);
#pragma unroll
    for (int nf = 0; nf < 8; nf++) {
        float bx = 0.f, by = 0.f;
        if (bias) { float2 bb = *(const float2*)&bias[colb + nf * 8]; bx = bb.x; by = bb.y; }
#pragma unroll
        for (int half = 0; half < 2; half++) {
            long long rr = r0 + half * 8;
            if (rr >= N_NODES) continue;
            float vx = acc[nf][half * 2 + 0] + bx;
            float vy = acc[nf][half * 2 + 1] + by;
            if (doRelu) { vx = fmaxf(vx, 0.f); vy = fmaxf(vy, 0.f); }
            long long oidx = rr * 128 + colb + nf * 8;
            if (mode == 1) {
                __half2 h = __floats2half2_rn(vx, vy);
                *(unsigned*)&Ch[oidx] = *(unsigned*)&h;
            } else {
                *(float2*)&Cf[oidx] = make_float2(vx, vy);
            }
        }
    }
}

// agg + bias + relu: out[n] = relu(in[n] + sum_neigh in[j] + bias), fp16 io
__global__ void k_aggbr(const __half* __restrict__ in, __half* __restrict__ out,
                        const float* __restrict__ bias) {
    int node = (blockIdx.x * blockDim.x + threadIdx.x) >> 5;
    int lane = threadIdx.x & 31;
    if (node >= N_NODES) return;
    const uint2* in2 = (const uint2*)in;
    uint2 s = in2[(long long)node * 32 + lane];
    float2 p0 = __half22float2(*(__half2*)&s.x);
    float2 p1 = __half22float2(*(__half2*)&s.y);
    float a0 = p0.x, a1 = p0.y, a2 = p1.x, a3 = p1.y;
    int j = g_rowptr[node], end = g_rowptr[node + 1];
    for (; j + 4 <= end; j += 4) {
        int c0 = g_col[j], c1 = g_col[j + 1], c2 = g_col[j + 2], c3 = g_col[j + 3];
        uint2 v0 = in2[(long long)c0 * 32 + lane];
        uint2 v1 = in2[(long long)c1 * 32 + lane];
        uint2 v2 = in2[(long long)c2 * 32 + lane];
        uint2 v3 = in2[(long long)c3 * 32 + lane];
        float2 q;
        q = __half22float2(*(__half2*)&v0.x); a0 += q.x; a1 += q.y;
        q = __half22float2(*(__half2*)&v0.y); a2 += q.x; a3 += q.y;
        q = __half22float2(*(__half2*)&v1.x); a0 += q.x; a1 += q.y;
        q = __half22float2(*(__half2*)&v1.y); a2 += q.x; a3 += q.y;
        q = __half22float2(*(__half2*)&v2.x); a0 += q.x; a1 += q.y;
        q = __half22float2(*(__half2*)&v2.y); a2 += q.x; a3 += q.y;
        q = __half22float2(*(__half2*)&v3.x); a0 += q.x; a1 += q.y;
        q = __half22float2(*(__half2*)&v3.y); a2 += q.x; a3 += q.y;
    }
    for (; j < end; j++) {
        uint2 v = in2[(long long)g_col[j] * 32 + lane];
        float2 q0 = __half22float2(*(__half2*)&v.x);
        float2 q1 = __half22float2(*(__half2*)&v.y);
        a0 += q0.x; a1 += q0.y; a2 += q1.x; a3 += q1.y;
    }
    float4 b = *(const float4*)&bias[lane * 4];
    a0 = fmaxf(a0 + b.x, 0.f);
    a1 = fmaxf(a1 + b.y, 0.f);
    a2 = fmaxf(a2 + b.z, 0.f);
    a3 = fmaxf(a3 + b.w, 0.f);
    __half2 h0 = __floats2half2_rn(a0, a1);
    __half2 h1 = __floats2half2_rn(a2, a3);
    ((uint2*)out)[(long long)node * 32 + lane] = make_uint2(*(unsigned*)&h0, *(unsigned*)&h1);
}

// pool (+ per-graph counts fused)
#define NODES_PER_BLK 128
__global__ void k_pool(const float* __restrict__ h, const void* batch) {
    int wide = g_flag;
    int f = threadIdx.x;
    int base = blockIdx.x * NODES_PER_BLK;
    int end = base + NODES_PER_BLK;
    if (end > N_NODES) end = N_NODES;
    float run = 0.0f;
    int cur = -1, nrun = 0;
    for (int n = base; n < end; n++) {
        int g = (int)ld_idx(batch, n, wide);
        if (g != cur) {
            if (cur >= 0) {
                atomicAdd(&g_pooled[cur * D + f], run);
                if (f == 0) atomicAdd(&g_cnt[cur], nrun);
            }
            cur = g; run = 0.0f; nrun = 0;
        }
        run += h[(long long)n * D + f];
        nrun++;
    }
    if (cur >= 0) {
        atomicAdd(&g_pooled[cur * D + f], run);
        if (f == 0) atomicAdd(&g_cnt[cur], nrun);
    }
}

__global__ void k_final(const float* __restrict__ Wlin, const float* __restrict__ blin,
                        float* __restrict__ out) {
    int g = blockIdx.x;
    int k = threadIdx.x;
    float c = (float)g_cnt[g];
    if (c < 1.0f) c = 1.0f;
    float v = g_pooled[g * D + k] / c;
    __shared__ float red[128];
    for (int j = 0; j < NOUT; j++) {
        red[k] = v * Wlin[k * NOUT + j];
        __syncthreads();
        for (int s = 64; s > 0; s >>= 1) {
            if (k < s) red[k] += red[k + s];
            __syncthreads();
        }
        if (k == 0) out[g * NOUT + j] = red[0] + blin[j];
        __syncthreads();
    }
}

// ---------------- launch ------------------------------------------------------
extern "C" void kernel_launch(void* const* d_in, const int* in_sizes, int n_in,
                              void* d_out, int out_size) {
    const float* x    = (const float*)d_in[0];
    const void*  ei   = d_in[1];
    const void*  batch= d_in[2];
    const float* b1a  = (const float*)d_in[4];
    const float* b1b  = (const float*)d_in[6];
    const float* b2a  = (const float*)d_in[8];
    const float* b2b  = (const float*)d_in[10];
    const float* Wlin = (const float*)d_in[11];
    const float* blin = (const float*)d_in[12];
    float* out = (float*)d_out;

    __half *fA, *fB, *w16;
    float* f32;
    cudaGetSymbolAddress((void**)&fA,  g_fA);
    cudaGetSymbolAddress((void**)&fB,  g_fB);
    cudaGetSymbolAddress((void**)&f32, g_f32);
    cudaGetSymbolAddress((void**)&w16, g_W);

    cudaFuncSetAttribute(k_gemm, cudaFuncAttributeMaxDynamicSharedMemorySize, SMEM_G);

    const int aggBlocks = (N_NODES * 32 + 255) / 256;

    // prep + CSR (ordered so launch #6 = first GEMM for ncu capture)
    k_zero_detect<<<448, 512>>>(ei);                                           // 1
    k_wprep<<<(4 * D * D + 255) / 256, 256>>>((const float*)d_in[3], (const float*)d_in[5],
                                              (const float*)d_in[7], (const float*)d_in[9]); // 2
    k_convx<<<(N_NODES * 32 + 255) / 256, 256>>>(x, fA);                       // 3
    k_hist<<<6250, 256>>>(ei);                                                 // 4
    k_scan1<<<NB_SCAN, 1024>>>();                                              // 5
    k_gemm<<<NT, 256, SMEM_G>>>(fA, w16,             nullptr, fB, f32, 0, 1);  // 6: u = x@W1a
    k_scan2<<<1, 1>>>();                                                       // 7
    k_scan3<<<NB_SCAN, 1024>>>();                                              // 8
    k_fill<<<6250, 256>>>(ei);                                                 // 9
    // layer1 (linearity: v = relu(u + agg(u) + b1a); h1 = relu(v@W1b + b1b))
    k_aggbr<<<aggBlocks, 256>>>(fB, fA, b1a);                                  // 10
    k_gemm<<<NT, 256, SMEM_G>>>(fA, w16 + D * D,     b1b, fB, f32, 1, 1);      // 11
    // layer2
    k_gemm<<<NT, 256, SMEM_G>>>(fB, w16 + 2 * D * D, nullptr, fA, f32, 0, 1);  // 12
    k_aggbr<<<aggBlocks, 256>>>(fA, fB, b2a);                                  // 13
    k_gemm<<<NT, 256, SMEM_G>>>(fB, w16 + 3 * D * D, b2b, fA, f32, 0, 0);      // 14
    // pool + classify
    k_pool<<<(N_NODES + NODES_PER_BLK - 1) / NODES_PER_BLK, 128>>>(f32, batch);// 15
    k_final<<<N_GRAPHS, 128>>>(Wlin, blin, out);                               // 16
}

// round 9
// speedup vs baseline: 3.1530x; 1.0832x over previous
#include <cuda_runtime.h>
#include <cuda_fp16.h>
#include <cstdint>

#define N_NODES  100000
#define N_EDGES  1600000
#define N_GRAPHS 1000
#define D        128
#define NOUT     6
#define TILE_M   64
#define NT       1563              // ceil(100000/64)
#define NB_SCAN  ((N_NODES + 1023) / 1024)   // 98

// ---------------- scratch (static device globals; no allocs allowed) ----------
__device__ __align__(16) __half g_fA[N_NODES * D];
__device__ __align__(16) __half g_fB[N_NODES * D];
__device__ __align__(16) float  g_f32[N_NODES * D];
__device__ int   g_rowptr[N_NODES + 1];
__device__ int   g_pos[N_NODES];
__device__ int   g_col[N_EDGES];
__device__ int   g_bsum[NB_SCAN];
__device__ __align__(16) float g_pooled[N_GRAPHS * D];
__device__ int   g_cnt[N_GRAPHS];
__device__ int   g_flag;
__device__ __align__(16) __half g_W[4 * D * D];   // [k][n] row-major fp16

// ---------------- helpers -----------------------------------------------------
__device__ __forceinline__ long long ld_idx(const void* p, long long i, int wide) {
    return wide ? ((const long long*)p)[i] : (long long)((const int*)p)[i];
}

// 1: zero scratch + dtype detect
__global__ void k_zero_detect(const void* ei) {
    int i = blockIdx.x * blockDim.x + threadIdx.x;
    if (blockIdx.x == 0 && threadIdx.x == 0) {
        const int* p = (const int*)ei;
        int wide = 1;
        for (int k = 0; k < 64; k++)
            if (p[2 * k + 1] != 0) { wide = 0; break; }
        g_flag = wide;
    }
    int total = N_NODES + N_GRAPHS * D + N_GRAPHS;
    for (; i < total; i += gridDim.x * blockDim.x) {
        if (i < N_NODES) g_pos[i] = 0;
        else if (i < N_NODES + N_GRAPHS * D) g_pooled[i - N_NODES] = 0.0f;
        else g_cnt[i - N_NODES - N_GRAPHS * D] = 0;
    }
}

// 2: weights -> fp16, keep [k][n] layout
__global__ void k_wprep(const float* __restrict__ Wa, const float* __restrict__ Wb,
                        const float* __restrict__ Wc, const float* __restrict__ Wd) {
    int idx = blockIdx.x * blockDim.x + threadIdx.x;
    if (idx >= 4 * D * D) return;
    int m = idx >> 14, j = idx & 16383;
    const float* W = (m == 0) ? Wa : (m == 1) ? Wb : (m == 2) ? Wc : Wd;
    g_W[idx] = __float2half_rn(W[j]);
}

// CSR build
__global__ void k_hist(const void* ei) {
    int wide = g_flag;
    int e = blockIdx.x * blockDim.x + threadIdx.x;
    for (; e < N_EDGES; e += gridDim.x * blockDim.x) {
        int dst = (int)ld_idx(ei, (long long)N_EDGES + e, wide);
        atomicAdd(&g_pos[dst], 1);
    }
}

__global__ void k_scan1() {
    __shared__ int s[1024];
    int t = threadIdx.x;
    int i = blockIdx.x * 1024 + t;
    int v = (i < N_NODES) ? g_pos[i] : 0;
    s[t] = v;
    __syncthreads();
    for (int off = 1; off < 1024; off <<= 1) {
        int x = (t >= off) ? s[t - off] : 0;
        __syncthreads();
        s[t] += x;
        __syncthreads();
    }
    if (i < N_NODES) g_rowptr[i + 1] = s[t];
    if (t == 1023) g_bsum[blockIdx.x] = s[1023];
}

// finalize rowptr with inline cross-block prefix AND write fill cursors
__global__ void k_scan3() {
    __shared__ int soff;
    int t = threadIdx.x;
    if (t == 0) {
        int run = 0;
        for (int b = 0; b < (int)blockIdx.x; b++) run += g_bsum[b];
        soff = run;
    }
    __syncthreads();
    int off = soff;
    int i = blockIdx.x * 1024 + t;
    if (i < N_NODES) {
        int v = g_rowptr[i + 1] + off;
        g_rowptr[i + 1] = v;
        if (i + 1 < N_NODES) g_pos[i + 1] = v;
    }
    if (i == 0) { g_rowptr[0] = 0; g_pos[0] = 0; }
}

__global__ void k_fill(const void* ei) {
    int wide = g_flag;
    int e = blockIdx.x * blockDim.x + threadIdx.x;
    for (; e < N_EDGES; e += gridDim.x * blockDim.x) {
        int src = (int)ld_idx(ei, e, wide);
        int dst = (int)ld_idx(ei, (long long)N_EDGES + e, wide);
        int p = atomicAdd(&g_pos[dst], 1);
        g_col[p] = src;
    }
}

// ---------------- fp16 single-pass tensor GEMM --------------------------------
// C[64 x 128] = A[64 x 128] @ W  (+bias, relu; out fp16 or f32; A fp16 or f32)
#define LDB    136
#define SM_W   0
#define SM_A   17408
#define SMEM_G ((17408 + 8704) * 2)     // 52224 bytes

__device__ __forceinline__ uint32_t smem_u32(const void* p) {
    uint32_t a;
    asm("{ .reg .u64 t; cvta.to.shared.u64 t, %1; cvt.u32.u64 %0, t; }" : "=r"(a) : "l"(p));
    return a;
}
__device__ __forceinline__ void ldsm4(uint32_t& r0, uint32_t& r1, uint32_t& r2, uint32_t& r3, uint32_t addr) {
    asm volatile("ldmatrix.sync.aligned.m8n8.x4.shared.b16 {%0,%1,%2,%3}, [%4];"
                 : "=r"(r0), "=r"(r1), "=r"(r2), "=r"(r3) : "r"(addr));
}
__device__ __forceinline__ void ldsm4t(uint32_t& r0, uint32_t& r1, uint32_t& r2, uint32_t& r3, uint32_t addr) {
    asm volatile("ldmatrix.sync.aligned.m8n8.x4.trans.shared.b16 {%0,%1,%2,%3}, [%4];"
                 : "=r"(r0), "=r"(r1), "=r"(r2), "=r"(r3) : "r"(addr));
}
__device__ __forceinline__ void mma_f16(float* c, uint32_t a0, uint32_t a1, uint32_t a2, uint32_t a3,
                                        uint32_t b0, uint32_t b1) {
    asm volatile("mma.sync.aligned.m16n8k16.row.col.f32.f16.f16.f32 "
                 "{%0,%1,%2,%3}, {%4,%5,%6,%7}, {%8,%9}, {%0,%1,%2,%3};"
                 : "+f"(c[0]), "+f"(c[1]), "+f"(c[2]), "+f"(c[3])
                 : "r"(a0), "r"(a1), "r"(a2), "r"(a3), "r"(b0), "r"(b1));
}
__device__ __forceinline__ void cpa16(uint32_t dst, const void* src, int srcsize) {
    asm volatile("cp.async.cg.shared.global [%0], [%1], 16, %2;"
                 :: "r"(dst), "l"(src), "r"(srcsize));
}

// mode: 0 = f32 out, 1 = fp16 out ; inF32: A source is f32 (convert in staging)
__global__ __launch_bounds__(256, 3)
void k_gemm(const __half* __restrict__ Ain, const float* __restrict__ Af32,
            const __half* __restrict__ W, const float* __restrict__ bias,
            __half* __restrict__ Ch, float* __restrict__ Cf,
            int doRelu, int mode, int inF32) {
    extern __shared__ __half sm[];
    const int t = threadIdx.x;
    uint32_t sb = smem_u32(sm);
    const long long blockRow = (long long)blockIdx.x * TILE_M;

    // stage W (2048 x 16B) via cp.async
#pragma unroll
    for (int i = 0; i < 8; i++) {
        int lin = t + i * 256;              // 0..2047
        int row = lin >> 4, c = (lin & 15) * 8;
        cpa16(sb + 2u * (SM_W + row * LDB + c), W + row * 128 + c, 16);
    }
    // stage A tile (1024 chunks of 8 halfs)
    if (inF32) {
#pragma unroll
        for (int i = 0; i < 4; i++) {
            int lin = t + i * 256;
            int row = lin >> 4, c = (lin & 15) * 8;
            long long gr = blockRow + row;
            float4 v0 = make_float4(0.f, 0.f, 0.f, 0.f);
            float4 v1 = v0;
            if (gr < N_NODES) {
                v0 = *(const float4*)&Af32[gr * 128 + c];
                v1 = *(const float4*)&Af32[gr * 128 + c + 4];
            }
            __half2 h0 = __floats2half2_rn(v0.x, v0.y);
            __half2 h1 = __floats2half2_rn(v0.z, v0.w);
            __half2 h2 = __floats2half2_rn(v1.x, v1.y);
            __half2 h3 = __floats2half2_rn(v1.z, v1.w);
            *(uint4*)&sm[SM_A + row * LDB + c] =
                make_uint4(*(unsigned*)&h0, *(unsigned*)&h1, *(unsigned*)&h2, *(unsigned*)&h3);
        }
    } else {
#pragma unroll
        for (int i = 0; i < 4; i++) {
            int lin = t + i * 256;
            int row = lin >> 4, c = (lin & 15) * 8;
            long long gr = blockRow + row;
            int ok = (gr < N_NODES) ? 16 : 0;
            long long src = (gr < N_NODES) ? gr : 0;
            cpa16(sb + 2u * (SM_A + row * LDB + c), Ain + src * 128 + c, ok);
        }
    }
    asm volatile("cp.async.commit_group;" ::: "memory");
    asm volatile("cp.async.wait_group 0;" ::: "memory");
    __syncthreads();

    const int w = t >> 5, lane = t & 31;
    const int mbase = (w >> 1) * 16;        // 4 m-warps x 16 rows
    const int nbase = (w & 1) * 64;         // 2 n-warps x 64 cols
    const int lrow = lane & 15;
    const int lcol = (lane >> 4) * 8;

    float acc[8][4];
#pragma unroll
    for (int nf = 0; nf < 8; nf++)
#pragma unroll
        for (int r = 0; r < 4; r++) acc[nf][r] = 0.f;

#pragma unroll
    for (int kk = 0; kk < 8; kk++) {
        const int k0 = kk * 16;
        uint32_t a0, a1, a2, a3;
        ldsm4(a0, a1, a2, a3, sb + 2u * (SM_A + (mbase + lrow) * LDB + k0 + lcol));
        uint32_t b[4][4];
#pragma unroll
        for (int ni = 0; ni < 4; ni++)
            ldsm4t(b[ni][0], b[ni][1], b[ni][2], b[ni][3],
                   sb + 2u * (SM_W + (k0 + lrow) * LDB + nbase + ni * 16 + lcol));
#pragma unroll
        for (int ni = 0; ni < 4; ni++) {
            mma_f16(acc[2 * ni],     a0, a1, a2, a3, b[ni][0], b[ni][1]);
            mma_f16(acc[2 * ni + 1], a0, a1, a2, a3, b[ni][2], b[ni][3]);
        }
    }

    // epilogue
    const int colb = nbase + 2 * (lane & 3);
    const long long r0 = blockRow + mbase + (lane >> 2);
#pragma unroll
    for (int nf = 0; nf < 8; nf++) {
        float bx = 0.f, by = 0.f;
        if (bias) { float2 bb = *(const float2*)&bias[colb + nf * 8]; bx = bb.x; by = bb.y; }
#pragma unroll
        for (int half = 0; half < 2; half++) {
            long long rr = r0 + half * 8;
            if (rr >= N_NODES) continue;
            float vx = acc[nf][half * 2 + 0] + bx;
            float vy = acc[nf][half * 2 + 1] + by;
            if (doRelu) { vx = fmaxf(vx, 0.f); vy = fmaxf(vy, 0.f); }
            long long oidx = rr * 128 + colb + nf * 8;
            if (mode == 1) {
                __half2 h = __floats2half2_rn(vx, vy);
                *(unsigned*)&Ch[oidx] = *(unsigned*)&h;
            } else {
                *(float2*)&Cf[oidx] = make_float2(vx, vy);
            }
        }
    }
}

// agg + bias + relu: out[n] = relu(in[n] + sum_neigh in[j] + bias), fp16 io
__global__ void k_aggbr(const __half* __restrict__ in, __half* __restrict__ out,
                        const float* __restrict__ bias) {
    int node = (blockIdx.x * blockDim.x + threadIdx.x) >> 5;
    int lane = threadIdx.x & 31;
    if (node >= N_NODES) return;
    const uint2* in2 = (const uint2*)in;
    uint2 s = in2[(long long)node * 32 + lane];
    float2 p0 = __half22float2(*(__half2*)&s.x);
    float2 p1 = __half22float2(*(__half2*)&s.y);
    float a0 = p0.x, a1 = p0.y, a2 = p1.x, a3 = p1.y;
    int j = g_rowptr[node], end = g_rowptr[node + 1];
    for (; j + 4 <= end; j += 4) {
        int c0 = g_col[j], c1 = g_col[j + 1], c2 = g_col[j + 2], c3 = g_col[j + 3];
        uint2 v0 = in2[(long long)c0 * 32 + lane];
        uint2 v1 = in2[(long long)c1 * 32 + lane];
        uint2 v2 = in2[(long long)c2 * 32 + lane];
        uint2 v3 = in2[(long long)c3 * 32 + lane];
        float2 q;
        q = __half22float2(*(__half2*)&v0.x); a0 += q.x; a1 += q.y;
        q = __half22float2(*(__half2*)&v0.y); a2 += q.x; a3 += q.y;
        q = __half22float2(*(__half2*)&v1.x); a0 += q.x; a1 += q.y;
        q = __half22float2(*(__half2*)&v1.y); a2 += q.x; a3 += q.y;
        q = __half22float2(*(__half2*)&v2.x); a0 += q.x; a1 += q.y;
        q = __half22float2(*(__half2*)&v2.y); a2 += q.x; a3 += q.y;
        q = __half22float2(*(__half2*)&v3.x); a0 += q.x; a1 += q.y;
        q = __half22float2(*(__half2*)&v3.y); a2 += q.x; a3 += q.y;
    }
    for (; j < end; j++) {
        uint2 v = in2[(long long)g_col[j] * 32 + lane];
        float2 q0 = __half22float2(*(__half2*)&v.x);
        float2 q1 = __half22float2(*(__half2*)&v.y);
        a0 += q0.x; a1 += q0.y; a2 += q1.x; a3 += q1.y;
    }
    float4 b = *(const float4*)&bias[lane * 4];
    a0 = fmaxf(a0 + b.x, 0.f);
    a1 = fmaxf(a1 + b.y, 0.f);
    a2 = fmaxf(a2 + b.z, 0.f);
    a3 = fmaxf(a3 + b.w, 0.f);
    __half2 h0 = __floats2half2_rn(a0, a1);
    __half2 h1 = __floats2half2_rn(a2, a3);
    ((uint2*)out)[(long long)node * 32 + lane] = make_uint2(*(unsigned*)&h0, *(unsigned*)&h1);
}

// pool (+ per-graph counts fused)
#define NODES_PER_BLK 128
__global__ void k_pool(const float* __restrict__ h, const void* batch) {
    int wide = g_flag;
    int f = threadIdx.x;
    int base = blockIdx.x * NODES_PER_BLK;
    int end = base + NODES_PER_BLK;
    if (end > N_NODES) end = N_NODES;
    float run = 0.0f;
    int cur = -1, nrun = 0;
    for (int n = base; n < end; n++) {
        int g = (int)ld_idx(batch, n, wide);
        if (g != cur) {
            if (cur >= 0) {
                atomicAdd(&g_pooled[cur * D + f], run);
                if (f == 0) atomicAdd(&g_cnt[cur], nrun);
            }
            cur = g; run = 0.0f; nrun = 0;
        }
        run += h[(long long)n * D + f];
        nrun++;
    }
    if (cur >= 0) {
        atomicAdd(&g_pooled[cur * D + f], run);
        if (f == 0) atomicAdd(&g_cnt[cur], nrun);
    }
}

__global__ void k_final(const float* __restrict__ Wlin, const float* __restrict__ blin,
                        float* __restrict__ out) {
    int g = blockIdx.x;
    int k = threadIdx.x;
    float c = (float)g_cnt[g];
    if (c < 1.0f) c = 1.0f;
    float v = g_pooled[g * D + k] / c;
    __shared__ float red[128];
    for (int j = 0; j < NOUT; j++) {
        red[k] = v * Wlin[k * NOUT + j];
        __syncthreads();
        for (int s = 64; s > 0; s >>= 1) {
            if (k < s) red[k] += red[k + s];
            __syncthreads();
        }
        if (k == 0) out[g * NOUT + j] = red[0] + blin[j];
        __syncthreads();
    }
}

// ---------------- launch ------------------------------------------------------
extern "C" void kernel_launch(void* const* d_in, const int* in_sizes, int n_in,
                              void* d_out, int out_size) {
    const float* x    = (const float*)d_in[0];
    const void*  ei   = d_in[1];
    const void*  batch= d_in[2];
    const float* b1a  = (const float*)d_in[4];
    const float* b1b  = (const float*)d_in[6];
    const float* b2a  = (const float*)d_in[8];
    const float* b2b  = (const float*)d_in[10];
    const float* Wlin = (const float*)d_in[11];
    const float* blin = (const float*)d_in[12];
    float* out = (float*)d_out;

    __half *fA, *fB, *w16;
    float* f32;
    cudaGetSymbolAddress((void**)&fA,  g_fA);
    cudaGetSymbolAddress((void**)&fB,  g_fB);
    cudaGetSymbolAddress((void**)&f32, g_f32);
    cudaGetSymbolAddress((void**)&w16, g_W);

    static cudaStream_t s2;
    static cudaEvent_t e1, e2;
    static int inited = 0;
    if (!inited) {
        cudaStreamCreateWithFlags(&s2, cudaStreamNonBlocking);
        cudaEventCreateWithFlags(&e1, cudaEventDisableTiming);
        cudaEventCreateWithFlags(&e2, cudaEventDisableTiming);
        cudaFuncSetAttribute(k_gemm, cudaFuncAttributeMaxDynamicSharedMemorySize, SMEM_G);
        inited = 1;
    }

    const int aggBlocks = (N_NODES * 32 + 255) / 256;

    // 1: zero + detect (both chains depend on it)
    k_zero_detect<<<448, 512>>>(ei);
    cudaEventRecord(e1, 0);

    // s0 chain: wprep -> gemm1 (fused f32->fp16 A conversion)
    k_wprep<<<(4 * D * D + 255) / 256, 256>>>((const float*)d_in[3], (const float*)d_in[5],
                                              (const float*)d_in[7], (const float*)d_in[9]);
    // s2 chain (forked): CSR build
    cudaStreamWaitEvent(s2, e1, 0);
    k_hist<<<6250, 256, 0, s2>>>(ei);
    k_gemm<<<NT, 256, SMEM_G>>>(nullptr, x, w16, nullptr, fB, f32, 0, 1, 1);  // u = x@W1a
    k_scan1<<<NB_SCAN, 1024, 0, s2>>>();
    k_scan3<<<NB_SCAN, 1024, 0, s2>>>();
    k_fill<<<6250, 256, 0, s2>>>(ei);
    cudaEventRecord(e2, s2);
    cudaStreamWaitEvent(0, e2, 0);

    // layer1: v = relu(u + agg(u) + b1a); h1 = relu(v@W1b + b1b)
    k_aggbr<<<aggBlocks, 256>>>(fB, fA, b1a);
    k_gemm<<<NT, 256, SMEM_G>>>(fA, nullptr, w16 + D * D, b1b, fB, f32, 1, 1, 0);
    // layer2
    k_gemm<<<NT, 256, SMEM_G>>>(fB, nullptr, w16 + 2 * D * D, nullptr, fA, f32, 0, 1, 0);
    k_aggbr<<<aggBlocks, 256>>>(fA, fB, b2a);
    k_gemm<<<NT, 256, SMEM_G>>>(fB, nullptr, w16 + 3 * D * D, b2b, fA, f32, 0, 0, 0);
    // pool + classify
    k_pool<<<(N_NODES + NODES_PER_BLK - 1) / NODES_PER_BLK, 128>>>(f32, batch);
    k_final<<<N_GRAPHS, 128>>>(Wlin, blin, out);
}

// round 10
// speedup vs baseline: 3.1750x; 1.0070x over previous
#include <cuda_runtime.h>
#include <cuda_fp16.h>
#include <cstdint>

#define N_NODES  100000
#define N_EDGES  1600000
#define N_GRAPHS 1000
#define D        128
#define NOUT     6
#define TILE_M   64
#define NT       1563              // ceil(100000/64)
#define TPC      4                 // tiles per CTA
#define GRID_G   ((NT + TPC - 1) / TPC)   // 391
#define NB_SCAN  ((N_NODES + 1023) / 1024)   // 98

// ---------------- scratch (static device globals; no allocs allowed) ----------
__device__ __align__(16) __half g_fA[N_NODES * D];
__device__ __align__(16) __half g_fB[N_NODES * D];
__device__ __align__(16) float  g_f32[N_NODES * D];
__device__ int   g_rowptr[N_NODES + 1];
__device__ int   g_pos[N_NODES];
__device__ int   g_col[N_EDGES];
__device__ int   g_bsum[NB_SCAN];
__device__ __align__(16) float g_pooled[N_GRAPHS * D];
__device__ int   g_cnt[N_GRAPHS];
__device__ int   g_flag;
__device__ __align__(16) __half g_W[4 * D * D];   // [k][n] row-major fp16

// ---------------- helpers -----------------------------------------------------
__device__ __forceinline__ long long ld_idx(const void* p, long long i, int wide) {
    return wide ? ((const long long*)p)[i] : (long long)((const int*)p)[i];
}

__global__ void k_zero_detect(const void* ei) {
    int i = blockIdx.x * blockDim.x + threadIdx.x;
    if (blockIdx.x == 0 && threadIdx.x == 0) {
        const int* p = (const int*)ei;
        int wide = 1;
        for (int k = 0; k < 64; k++)
            if (p[2 * k + 1] != 0) { wide = 0; break; }
        g_flag = wide;
    }
    int total = N_NODES + N_GRAPHS * D + N_GRAPHS;
    for (; i < total; i += gridDim.x * blockDim.x) {
        if (i < N_NODES) g_pos[i] = 0;
        else if (i < N_NODES + N_GRAPHS * D) g_pooled[i - N_NODES] = 0.0f;
        else g_cnt[i - N_NODES - N_GRAPHS * D] = 0;
    }
}

__global__ void k_wprep(const float* __restrict__ Wa, const float* __restrict__ Wb,
                        const float* __restrict__ Wc, const float* __restrict__ Wd) {
    int idx = blockIdx.x * blockDim.x + threadIdx.x;
    if (idx >= 4 * D * D) return;
    int m = idx >> 14, j = idx & 16383;
    const float* W = (m == 0) ? Wa : (m == 1) ? Wb : (m == 2) ? Wc : Wd;
    g_W[idx] = __float2half_rn(W[j]);
}

// CSR build
__global__ void k_hist(const void* ei) {
    int wide = g_flag;
    int e = blockIdx.x * blockDim.x + threadIdx.x;
    for (; e < N_EDGES; e += gridDim.x * blockDim.x) {
        int dst = (int)ld_idx(ei, (long long)N_EDGES + e, wide);
        atomicAdd(&g_pos[dst], 1);
    }
}

__global__ void k_scan1() {
    __shared__ int s[1024];
    int t = threadIdx.x;
    int i = blockIdx.x * 1024 + t;
    int v = (i < N_NODES) ? g_pos[i] : 0;
    s[t] = v;
    __syncthreads();
    for (int off = 1; off < 1024; off <<= 1) {
        int x = (t >= off) ? s[t - off] : 0;
        __syncthreads();
        s[t] += x;
        __syncthreads();
    }
    if (i < N_NODES) g_rowptr[i + 1] = s[t];
    if (t == 1023) g_bsum[blockIdx.x] = s[1023];
}

__global__ void k_scan3() {
    __shared__ int soff;
    int t = threadIdx.x;
    if (t == 0) {
        int run = 0;
        for (int b = 0; b < (int)blockIdx.x; b++) run += g_bsum[b];
        soff = run;
    }
    __syncthreads();
    int off = soff;
    int i = blockIdx.x * 1024 + t;
    if (i < N_NODES) {
        int v = g_rowptr[i + 1] + off;
        g_rowptr[i + 1] = v;
        if (i + 1 < N_NODES) g_pos[i + 1] = v;
    }
    if (i == 0) { g_rowptr[0] = 0; g_pos[0] = 0; }
}

__global__ void k_fill(const void* ei) {
    int wide = g_flag;
    int e = blockIdx.x * blockDim.x + threadIdx.x;
    for (; e < N_EDGES; e += gridDim.x * blockDim.x) {
        int src = (int)ld_idx(ei, e, wide);
        int dst = (int)ld_idx(ei, (long long)N_EDGES + e, wide);
        int p = atomicAdd(&g_pos[dst], 1);
        g_col[p] = src;
    }
}

// ---------------- fp16 tensor GEMM: 4 tiles/CTA, A double-buffered ------------
#define LDB    136
#define SM_W   0
#define SM_A0  17408
#define A_SZ   8704                      // 64 * LDB
#define SMEM_G ((17408 + 2 * A_SZ) * 2)  // 69632 bytes

__device__ __forceinline__ uint32_t smem_u32(const void* p) {
    uint32_t a;
    asm("{ .reg .u64 t; cvta.to.shared.u64 t, %1; cvt.u32.u64 %0, t; }" : "=r"(a) : "l"(p));
    return a;
}
__device__ __forceinline__ void ldsm4(uint32_t& r0, uint32_t& r1, uint32_t& r2, uint32_t& r3, uint32_t addr) {
    asm volatile("ldmatrix.sync.aligned.m8n8.x4.shared.b16 {%0,%1,%2,%3}, [%4];"
                 : "=r"(r0), "=r"(r1), "=r"(r2), "=r"(r3) : "r"(addr));
}
__device__ __forceinline__ void ldsm4t(uint32_t& r0, uint32_t& r1, uint32_t& r2, uint32_t& r3, uint32_t addr) {
    asm volatile("ldmatrix.sync.aligned.m8n8.x4.trans.shared.b16 {%0,%1,%2,%3}, [%4];"
                 : "=r"(r0), "=r"(r1), "=r"(r2), "=r"(r3) : "r"(addr));
}
__device__ __forceinline__ void mma_f16(float* c, uint32_t a0, uint32_t a1, uint32_t a2, uint32_t a3,
                                        uint32_t b0, uint32_t b1) {
    asm volatile("mma.sync.aligned.m16n8k16.row.col.f32.f16.f16.f32 "
                 "{%0,%1,%2,%3}, {%4,%5,%6,%7}, {%8,%9}, {%0,%1,%2,%3};"
                 : "+f"(c[0]), "+f"(c[1]), "+f"(c[2]), "+f"(c[3])
                 : "r"(a0), "r"(a1), "r"(a2), "r"(a3), "r"(b0), "r"(b1));
}
__device__ __forceinline__ void cpa16(uint32_t dst, const void* src, int srcsize) {
    asm volatile("cp.async.cg.shared.global [%0], [%1], 16, %2;"
                 :: "r"(dst), "l"(src), "r"(srcsize));
}

// stage one 64x128 A tile into buffer buf (0/1)
__device__ __forceinline__ void stageA(__half* sm, uint32_t sb, int buf, int tile,
                                       const __half* __restrict__ Ain,
                                       const float* __restrict__ Af32, int inF32, int t) {
    const int base = SM_A0 + buf * A_SZ;
    const long long blockRow = (long long)tile * TILE_M;
    if (inF32) {
#pragma unroll
        for (int i = 0; i < 4; i++) {
            int lin = t + i * 256;
            int row = lin >> 4, c = (lin & 15) * 8;
            long long gr = blockRow + row;
            float4 v0 = make_float4(0.f, 0.f, 0.f, 0.f), v1 = v0;
            if (gr < N_NODES) {
                v0 = *(const float4*)&Af32[gr * 128 + c];
                v1 = *(const float4*)&Af32[gr * 128 + c + 4];
            }
            __half2 h0 = __floats2half2_rn(v0.x, v0.y);
            __half2 h1 = __floats2half2_rn(v0.z, v0.w);
            __half2 h2 = __floats2half2_rn(v1.x, v1.y);
            __half2 h3 = __floats2half2_rn(v1.z, v1.w);
            *(uint4*)&sm[base + row * LDB + c] =
                make_uint4(*(unsigned*)&h0, *(unsigned*)&h1, *(unsigned*)&h2, *(unsigned*)&h3);
        }
    } else {
#pragma unroll
        for (int i = 0; i < 4; i++) {
            int lin = t + i * 256;
            int row = lin >> 4, c = (lin & 15) * 8;
            long long gr = blockRow + row;
            int ok = (gr < N_NODES) ? 16 : 0;
            long long src = (gr < N_NODES) ? gr : 0;
            cpa16(sb + 2u * (base + row * LDB + c), Ain + src * 128 + c, ok);
        }
    }
}

// mode: 0 = f32 out, 1 = fp16 out ; inF32: A source is f32
__global__ __launch_bounds__(256, 3)
void k_gemm(const __half* __restrict__ Ain, const float* __restrict__ Af32,
            const __half* __restrict__ W, const float* __restrict__ bias,
            __half* __restrict__ Ch, float* __restrict__ Cf,
            int doRelu, int mode, int inF32) {
    extern __shared__ __half sm[];
    const int t = threadIdx.x;
    uint32_t sb = smem_u32(sm);

    // stage W once (2048 x 16B)
#pragma unroll
    for (int i = 0; i < 8; i++) {
        int lin = t + i * 256;
        int row = lin >> 4, c = (lin & 15) * 8;
        cpa16(sb + 2u * (SM_W + row * LDB + c), W + row * 128 + c, 16);
    }
    // stage first A tile
    int tile0 = blockIdx.x * TPC;
    stageA(sm, sb, 0, tile0, Ain, Af32, inF32, t);
    asm volatile("cp.async.commit_group;" ::: "memory");      // G0 = {W, A0}

    const int w = t >> 5, lane = t & 31;
    const int mbase = (w >> 1) * 16;
    const int nbase = (w & 1) * 64;
    const int lrow = lane & 15;
    const int lcol = (lane >> 4) * 8;
    const int colb = nbase + 2 * (lane & 3);

    float bx[8], by[8];
#pragma unroll
    for (int nf = 0; nf < 8; nf++) {
        bx[nf] = 0.f; by[nf] = 0.f;
        if (bias) { float2 bb = *(const float2*)&bias[colb + nf * 8]; bx[nf] = bb.x; by[nf] = bb.y; }
    }

    int buf = 0;
#pragma unroll
    for (int it = 0; it < TPC; it++) {
        int tile = blockIdx.x * TPC + it;
        if (tile >= NT) break;
        int havenext = (it + 1 < TPC) && (tile + 1 < NT);
        if (havenext) stageA(sm, sb, buf ^ 1, tile + 1, Ain, Af32, inF32, t);
        asm volatile("cp.async.commit_group;" ::: "memory");
        if (havenext) asm volatile("cp.async.wait_group 1;" ::: "memory");
        else          asm volatile("cp.async.wait_group 0;" ::: "memory");
        __syncthreads();

        float acc[8][4];
#pragma unroll
        for (int nf = 0; nf < 8; nf++)
#pragma unroll
            for (int r = 0; r < 4; r++) acc[nf][r] = 0.f;

        const int aBase = SM_A0 + buf * A_SZ;
#pragma unroll
        for (int kk = 0; kk < 8; kk++) {
            const int k0 = kk * 16;
            uint32_t a0, a1, a2, a3;
            ldsm4(a0, a1, a2, a3, sb + 2u * (aBase + (mbase + lrow) * LDB + k0 + lcol));
            uint32_t b[4][4];
#pragma unroll
            for (int ni = 0; ni < 4; ni++)
                ldsm4t(b[ni][0], b[ni][1], b[ni][2], b[ni][3],
                       sb + 2u * (SM_W + (k0 + lrow) * LDB + nbase + ni * 16 + lcol));
#pragma unroll
            for (int ni = 0; ni < 4; ni++) {
                mma_f16(acc[2 * ni],     a0, a1, a2, a3, b[ni][0], b[ni][1]);
                mma_f16(acc[2 * ni + 1], a0, a1, a2, a3, b[ni][2], b[ni][3]);
            }
        }

        // epilogue
        const long long r0 = (long long)tile * TILE_M + mbase + (lane >> 2);
#pragma unroll
        for (int nf = 0; nf < 8; nf++) {
#pragma unroll
            for (int half = 0; half < 2; half++) {
                long long rr = r0 + half * 8;
                if (rr >= N_NODES) continue;
                float vx = acc[nf][half * 2 + 0] + bx[nf];
                float vy = acc[nf][half * 2 + 1] + by[nf];
                if (doRelu) { vx = fmaxf(vx, 0.f); vy = fmaxf(vy, 0.f); }
                long long oidx = rr * 128 + colb + nf * 8;
                if (mode == 1) {
                    __half2 h = __floats2half2_rn(vx, vy);
                    *(unsigned*)&Ch[oidx] = *(unsigned*)&h;
                } else {
                    *(float2*)&Cf[oidx] = make_float2(vx, vy);
                }
            }
        }
        __syncthreads();
        buf ^= 1;
    }
}

// agg + bias + relu: out[n] = relu(in[n] + sum_neigh in[j] + bias), fp16 io
__global__ void k_aggbr(const __half* __restrict__ in, __half* __restrict__ out,
                        const float* __restrict__ bias) {
    int node = (blockIdx.x * blockDim.x + threadIdx.x) >> 5;
    int lane = threadIdx.x & 31;
    if (node >= N_NODES) return;
    const uint2* in2 = (const uint2*)in;
    uint2 s = in2[(long long)node * 32 + lane];
    float2 p0 = __half22float2(*(__half2*)&s.x);
    float2 p1 = __half22float2(*(__half2*)&s.y);
    float a0 = p0.x, a1 = p0.y, a2 = p1.x, a3 = p1.y;
    int j = g_rowptr[node], end = g_rowptr[node + 1];
    for (; j + 4 <= end; j += 4) {
        int c0 = g_col[j], c1 = g_col[j + 1], c2 = g_col[j + 2], c3 = g_col[j + 3];
        uint2 v0 = in2[(long long)c0 * 32 + lane];
        uint2 v1 = in2[(long long)c1 * 32 + lane];
        uint2 v2 = in2[(long long)c2 * 32 + lane];
        uint2 v3 = in2[(long long)c3 * 32 + lane];
        float2 q;
        q = __half22float2(*(__half2*)&v0.x); a0 += q.x; a1 += q.y;
        q = __half22float2(*(__half2*)&v0.y); a2 += q.x; a3 += q.y;
        q = __half22float2(*(__half2*)&v1.x); a0 += q.x; a1 += q.y;
        q = __half22float2(*(__half2*)&v1.y); a2 += q.x; a3 += q.y;
        q = __half22float2(*(__half2*)&v2.x); a0 += q.x; a1 += q.y;
        q = __half22float2(*(__half2*)&v2.y); a2 += q.x; a3 += q.y;
        q = __half22float2(*(__half2*)&v3.x); a0 += q.x; a1 += q.y;
        q = __half22float2(*(__half2*)&v3.y); a2 += q.x; a3 += q.y;
    }
    for (; j < end; j++) {
        uint2 v = in2[(long long)g_col[j] * 32 + lane];
        float2 q0 = __half22float2(*(__half2*)&v.x);
        float2 q1 = __half22float2(*(__half2*)&v.y);
        a0 += q0.x; a1 += q0.y; a2 += q1.x; a3 += q1.y;
    }
    float4 b = *(const float4*)&bias[lane * 4];
    a0 = fmaxf(a0 + b.x, 0.f);
    a1 = fmaxf(a1 + b.y, 0.f);
    a2 = fmaxf(a2 + b.z, 0.f);
    a3 = fmaxf(a3 + b.w, 0.f);
    __half2 h0 = __floats2half2_rn(a0, a1);
    __half2 h1 = __floats2half2_rn(a2, a3);
    ((uint2*)out)[(long long)node * 32 + lane] = make_uint2(*(unsigned*)&h0, *(unsigned*)&h1);
}

// pool (+ per-graph counts fused)
#define NODES_PER_BLK 128
__global__ void k_pool(const float* __restrict__ h, const void* batch) {
    int wide = g_flag;
    int f = threadIdx.x;
    int base = blockIdx.x * NODES_PER_BLK;
    int end = base + NODES_PER_BLK;
    if (end > N_NODES) end = N_NODES;
    float run = 0.0f;
    int cur = -1, nrun = 0;
    for (int n = base; n < end; n++) {
        int g = (int)ld_idx(batch, n, wide);
        if (g != cur) {
            if (cur >= 0) {
                atomicAdd(&g_pooled[cur * D + f], run);
                if (f == 0) atomicAdd(&g_cnt[cur], nrun);
            }
            cur = g; run = 0.0f; nrun = 0;
        }
        run += h[(long long)n * D + f];
        nrun++;
    }
    if (cur >= 0) {
        atomicAdd(&g_pooled[cur * D + f], run);
        if (f == 0) atomicAdd(&g_cnt[cur], nrun);
    }
}

__global__ void k_final(const float* __restrict__ Wlin, const float* __restrict__ blin,
                        float* __restrict__ out) {
    int g = blockIdx.x;
    int k = threadIdx.x;
    float c = (float)g_cnt[g];
    if (c < 1.0f) c = 1.0f;
    float v = g_pooled[g * D + k] / c;
    __shared__ float red[128];
    for (int j = 0; j < NOUT; j++) {
        red[k] = v * Wlin[k * NOUT + j];
        __syncthreads();
        for (int s = 64; s > 0; s >>= 1) {
            if (k < s) red[k] += red[k + s];
            __syncthreads();
        }
        if (k == 0) out[g * NOUT + j] = red[0] + blin[j];
        __syncthreads();
    }
}

// ---------------- launch ------------------------------------------------------
extern "C" void kernel_launch(void* const* d_in, const int* in_sizes, int n_in,
                              void* d_out, int out_size) {
    const float* x    = (const float*)d_in[0];
    const void*  ei   = d_in[1];
    const void*  batch= d_in[2];
    const float* b1a  = (const float*)d_in[4];
    const float* b1b  = (const float*)d_in[6];
    const float* b2a  = (const float*)d_in[8];
    const float* b2b  = (const float*)d_in[10];
    const float* Wlin = (const float*)d_in[11];
    const float* blin = (const float*)d_in[12];
    float* out = (float*)d_out;

    __half *fA, *fB, *w16;
    float* f32;
    cudaGetSymbolAddress((void**)&fA,  g_fA);
    cudaGetSymbolAddress((void**)&fB,  g_fB);
    cudaGetSymbolAddress((void**)&f32, g_f32);
    cudaGetSymbolAddress((void**)&w16, g_W);

    static cudaStream_t s2;
    static cudaEvent_t e1, e2;
    static int inited = 0;
    if (!inited) {
        cudaStreamCreateWithFlags(&s2, cudaStreamNonBlocking);
        cudaEventCreateWithFlags(&e1, cudaEventDisableTiming);
        cudaEventCreateWithFlags(&e2, cudaEventDisableTiming);
        cudaFuncSetAttribute(k_gemm, cudaFuncAttributeMaxDynamicSharedMemorySize, SMEM_G);
        inited = 1;
    }

    const int aggBlocks = (N_NODES * 32 + 255) / 256;

    k_zero_detect<<<448, 512>>>(ei);
    cudaEventRecord(e1, 0);

    // s0 chain: wprep -> gemm1 (A = f32 x, converted in staging)
    k_wprep<<<(4 * D * D + 255) / 256, 256>>>((const float*)d_in[3], (const float*)d_in[5],
                                              (const float*)d_in[7], (const float*)d_in[9]);
    // s2 chain (forked): CSR build
    cudaStreamWaitEvent(s2, e1, 0);
    k_hist<<<6250, 256, 0, s2>>>(ei);
    k_gemm<<<GRID_G, 256, SMEM_G>>>(nullptr, x, w16, nullptr, fB, f32, 0, 1, 1);  // u = x@W1a
    k_scan1<<<NB_SCAN, 1024, 0, s2>>>();
    k_scan3<<<NB_SCAN, 1024, 0, s2>>>();
    k_fill<<<6250, 256, 0, s2>>>(ei);
    cudaEventRecord(e2, s2);
    cudaStreamWaitEvent(0, e2, 0);

    // layer1: v = relu(u + agg(u) + b1a); h1 = relu(v@W1b + b1b)
    k_aggbr<<<aggBlocks, 256>>>(fB, fA, b1a);
    k_gemm<<<GRID_G, 256, SMEM_G>>>(fA, nullptr, w16 + D * D, b1b, fB, f32, 1, 1, 0);
    // layer2
    k_gemm<<<GRID_G, 256, SMEM_G>>>(fB, nullptr, w16 + 2 * D * D, nullptr, fA, f32, 0, 1, 0);
    k_aggbr<<<aggBlocks, 256>>>(fA, fB, b2a);
    k_gemm<<<GRID_G, 256, SMEM_G>>>(fB, nullptr, w16 + 3 * D * D, b2b, fA, f32, 0, 0, 0);
    // pool + classify
    k_pool<<<(N_NODES + NODES_PER_BLK - 1) / NODES_PER_BLK, 128>>>(f32, batch);
    k_final<<<N_GRAPHS, 128>>>(Wlin, blin, out);
}

// round 11
// speedup vs baseline: 3.1997x; 1.0078x over previous
#include <cuda_runtime.h>
#include <cuda_fp16.h>
#include <cstdint>

#define N_NODES  100000
#define N_EDGES  1600000
#define N_GRAPHS 1000
#define D        128
#define NOUT     6
#define TILE_M   64
#define NT       1563              // ceil(100000/64)
#define NB_SCAN  ((N_NODES + 1023) / 1024)   // 98

// ---------------- scratch (static device globals; no allocs allowed) ----------
__device__ __align__(16) __half g_fA[N_NODES * D];
__device__ __align__(16) __half g_fB[N_NODES * D];
__device__ int   g_rowptr[N_NODES + 1];
__device__ int   g_pos[N_NODES];
__device__ int   g_col[N_EDGES];
__device__ int   g_bsum[NB_SCAN];
__device__ __align__(16) float g_pooled[N_GRAPHS * D];
__device__ int   g_cnt[N_GRAPHS];
__device__ int   g_flag;
__device__ __align__(16) __half g_W[4 * D * D];   // [k][n] row-major fp16

// ---------------- helpers -----------------------------------------------------
__device__ __forceinline__ long long ld_idx(const void* p, long long i, int wide) {
    return wide ? ((const long long*)p)[i] : (long long)((const int*)p)[i];
}

__global__ void k_zero_detect(const void* ei) {
    int i = blockIdx.x * blockDim.x + threadIdx.x;
    if (blockIdx.x == 0 && threadIdx.x == 0) {
        const int* p = (const int*)ei;
        int wide = 1;
        for (int k = 0; k < 64; k++)
            if (p[2 * k + 1] != 0) { wide = 0; break; }
        g_flag = wide;
    }
    int total = N_NODES + N_GRAPHS * D + N_GRAPHS;
    for (; i < total; i += gridDim.x * blockDim.x) {
        if (i < N_NODES) g_pos[i] = 0;
        else if (i < N_NODES + N_GRAPHS * D) g_pooled[i - N_NODES] = 0.0f;
        else g_cnt[i - N_NODES - N_GRAPHS * D] = 0;
    }
}

__global__ void k_wprep(const float* __restrict__ Wa, const float* __restrict__ Wb,
                        const float* __restrict__ Wc, const float* __restrict__ Wd) {
    int idx = blockIdx.x * blockDim.x + threadIdx.x;
    if (idx >= 4 * D * D) return;
    int m = idx >> 14, j = idx & 16383;
    const float* W = (m == 0) ? Wa : (m == 1) ? Wb : (m == 2) ? Wc : Wd;
    g_W[idx] = __float2half_rn(W[j]);
}

// CSR build
__global__ void k_hist(const void* ei) {
    int wide = g_flag;
    int e = blockIdx.x * blockDim.x + threadIdx.x;
    for (; e < N_EDGES; e += gridDim.x * blockDim.x) {
        int dst = (int)ld_idx(ei, (long long)N_EDGES + e, wide);
        atomicAdd(&g_pos[dst], 1);
    }
}

__global__ void k_scan1() {
    __shared__ int s[1024];
    int t = threadIdx.x;
    int i = blockIdx.x * 1024 + t;
    int v = (i < N_NODES) ? g_pos[i] : 0;
    s[t] = v;
    __syncthreads();
    for (int off = 1; off < 1024; off <<= 1) {
        int x = (t >= off) ? s[t - off] : 0;
        __syncthreads();
        s[t] += x;
        __syncthreads();
    }
    if (i < N_NODES) g_rowptr[i + 1] = s[t];
    if (t == 1023) g_bsum[blockIdx.x] = s[1023];
}

__global__ void k_scan3() {
    __shared__ int soff;
    int t = threadIdx.x;
    if (t == 0) {
        int run = 0;
        for (int b = 0; b < (int)blockIdx.x; b++) run += g_bsum[b];
        soff = run;
    }
    __syncthreads();
    int off = soff;
    int i = blockIdx.x * 1024 + t;
    if (i < N_NODES) {
        int v = g_rowptr[i + 1] + off;
        g_rowptr[i + 1] = v;
        if (i + 1 < N_NODES) g_pos[i + 1] = v;
    }
    if (i == 0) { g_rowptr[0] = 0; g_pos[0] = 0; }
}

__global__ void k_fill(const void* ei) {
    int wide = g_flag;
    int e = blockIdx.x * blockDim.x + threadIdx.x;
    for (; e < N_EDGES; e += gridDim.x * blockDim.x) {
        int src = (int)ld_idx(ei, e, wide);
        int dst = (int)ld_idx(ei, (long long)N_EDGES + e, wide);
        int p = atomicAdd(&g_pos[dst], 1);
        g_col[p] = src;
    }
}

// ---------------- fp16 tensor GEMM: runtime tiles/CTA, A double-buffered ------
#define LDB    136
#define SM_W   0
#define SM_A0  17408
#define A_SZ   8704                      // 64 * LDB
#define SMEM_G ((17408 + 2 * A_SZ) * 2)  // 69632 bytes

__device__ __forceinline__ uint32_t smem_u32(const void* p) {
    uint32_t a;
    asm("{ .reg .u64 t; cvta.to.shared.u64 t, %1; cvt.u32.u64 %0, t; }" : "=r"(a) : "l"(p));
    return a;
}
__device__ __forceinline__ void ldsm4(uint32_t& r0, uint32_t& r1, uint32_t& r2, uint32_t& r3, uint32_t addr) {
    asm volatile("ldmatrix.sync.aligned.m8n8.x4.shared.b16 {%0,%1,%2,%3}, [%4];"
                 : "=r"(r0), "=r"(r1), "=r"(r2), "=r"(r3) : "r"(addr));
}
__device__ __forceinline__ void ldsm4t(uint32_t& r0, uint32_t& r1, uint32_t& r2, uint32_t& r3, uint32_t addr) {
    asm volatile("ldmatrix.sync.aligned.m8n8.x4.trans.shared.b16 {%0,%1,%2,%3}, [%4];"
                 : "=r"(r0), "=r"(r1), "=r"(r2), "=r"(r3) : "r"(addr));
}
__device__ __forceinline__ void mma_f16(float* c, uint32_t a0, uint32_t a1, uint32_t a2, uint32_t a3,
                                        uint32_t b0, uint32_t b1) {
    asm volatile("mma.sync.aligned.m16n8k16.row.col.f32.f16.f16.f32 "
                 "{%0,%1,%2,%3}, {%4,%5,%6,%7}, {%8,%9}, {%0,%1,%2,%3};"
                 : "+f"(c[0]), "+f"(c[1]), "+f"(c[2]), "+f"(c[3])
                 : "r"(a0), "r"(a1), "r"(a2), "r"(a3), "r"(b0), "r"(b1));
}
__device__ __forceinline__ void cpa16(uint32_t dst, const void* src, int srcsize) {
    asm volatile("cp.async.cg.shared.global [%0], [%1], 16, %2;"
                 :: "r"(dst), "l"(src), "r"(srcsize));
}

__device__ __forceinline__ void stageA(__half* sm, uint32_t sb, int buf, int tile,
                                       const __half* __restrict__ Ain,
                                       const float* __restrict__ Af32, int inF32, int t) {
    const int base = SM_A0 + buf * A_SZ;
    const long long blockRow = (long long)tile * TILE_M;
    if (inF32) {
#pragma unroll
        for (int i = 0; i < 4; i++) {
            int lin = t + i * 256;
            int row = lin >> 4, c = (lin & 15) * 8;
            long long gr = blockRow + row;
            float4 v0 = make_float4(0.f, 0.f, 0.f, 0.f), v1 = v0;
            if (gr < N_NODES) {
                v0 = *(const float4*)&Af32[gr * 128 + c];
                v1 = *(const float4*)&Af32[gr * 128 + c + 4];
            }
            __half2 h0 = __floats2half2_rn(v0.x, v0.y);
            __half2 h1 = __floats2half2_rn(v0.z, v0.w);
            __half2 h2 = __floats2half2_rn(v1.x, v1.y);
            __half2 h3 = __floats2half2_rn(v1.z, v1.w);
            *(uint4*)&sm[base + row * LDB + c] =
                make_uint4(*(unsigned*)&h0, *(unsigned*)&h1, *(unsigned*)&h2, *(unsigned*)&h3);
        }
    } else {
#pragma unroll
        for (int i = 0; i < 4; i++) {
            int lin = t + i * 256;
            int row = lin >> 4, c = (lin & 15) * 8;
            long long gr = blockRow + row;
            int ok = (gr < N_NODES) ? 16 : 0;
            long long src = (gr < N_NODES) ? gr : 0;
            cpa16(sb + 2u * (base + row * LDB + c), Ain + src * 128 + c, ok);
        }
    }
}

// mode: 0 = f32 out, 1 = fp16 out ; inF32: A source is f32 ; tpc: tiles per CTA
__global__ __launch_bounds__(256, 3)
void k_gemm(const __half* __restrict__ Ain, const float* __restrict__ Af32,
            const __half* __restrict__ W, const float* __restrict__ bias,
            __half* __restrict__ Ch, float* __restrict__ Cf,
            int doRelu, int mode, int inF32, int tpc) {
    extern __shared__ __half sm[];
    const int t = threadIdx.x;
    uint32_t sb = smem_u32(sm);

    // stage W once
#pragma unroll
    for (int i = 0; i < 8; i++) {
        int lin = t + i * 256;
        int row = lin >> 4, c = (lin & 15) * 8;
        cpa16(sb + 2u * (SM_W + row * LDB + c), W + row * 128 + c, 16);
    }
    int tile0 = blockIdx.x * tpc;
    if (tile0 >= NT) return;
    stageA(sm, sb, 0, tile0, Ain, Af32, inF32, t);
    asm volatile("cp.async.commit_group;" ::: "memory");

    const int w = t >> 5, lane = t & 31;
    const int mbase = (w >> 1) * 16;
    const int nbase = (w & 1) * 64;
    const int lrow = lane & 15;
    const int lcol = (lane >> 4) * 8;
    const int colb = nbase + 2 * (lane & 3);

    float bx[8], by[8];
#pragma unroll
    for (int nf = 0; nf < 8; nf++) {
        bx[nf] = 0.f; by[nf] = 0.f;
        if (bias) { float2 bb = *(const float2*)&bias[colb + nf * 8]; bx[nf] = bb.x; by[nf] = bb.y; }
    }

    int buf = 0;
    for (int it = 0; it < tpc; it++) {
        int tile = tile0 + it;
        if (tile >= NT) break;
        int havenext = (it + 1 < tpc) && (tile + 1 < NT);
        if (havenext) stageA(sm, sb, buf ^ 1, tile + 1, Ain, Af32, inF32, t);
        asm volatile("cp.async.commit_group;" ::: "memory");
        if (havenext) asm volatile("cp.async.wait_group 1;" ::: "memory");
        else          asm volatile("cp.async.wait_group 0;" ::: "memory");
        __syncthreads();

        float acc[8][4];
#pragma unroll
        for (int nf = 0; nf < 8; nf++)
#pragma unroll
            for (int r = 0; r < 4; r++) acc[nf][r] = 0.f;

        const int aBase = SM_A0 + buf * A_SZ;
#pragma unroll
        for (int kk = 0; kk < 8; kk++) {
            const int k0 = kk * 16;
            uint32_t a0, a1, a2, a3;
            ldsm4(a0, a1, a2, a3, sb + 2u * (aBase + (mbase + lrow) * LDB + k0 + lcol));
            uint32_t b[4][4];
#pragma unroll
            for (int ni = 0; ni < 4; ni++)
                ldsm4t(b[ni][0], b[ni][1], b[ni][2], b[ni][3],
                       sb + 2u * (SM_W + (k0 + lrow) * LDB + nbase + ni * 16 + lcol));
#pragma unroll
            for (int ni = 0; ni < 4; ni++) {
                mma_f16(acc[2 * ni],     a0, a1, a2, a3, b[ni][0], b[ni][1]);
                mma_f16(acc[2 * ni + 1], a0, a1, a2, a3, b[ni][2], b[ni][3]);
            }
        }

        const long long r0 = (long long)tile * TILE_M + mbase + (lane >> 2);
#pragma unroll
        for (int nf = 0; nf < 8; nf++) {
#pragma unroll
            for (int half = 0; half < 2; half++) {
                long long rr = r0 + half * 8;
                if (rr >= N_NODES) continue;
                float vx = acc[nf][half * 2 + 0] + bx[nf];
                float vy = acc[nf][half * 2 + 1] + by[nf];
                if (doRelu) { vx = fmaxf(vx, 0.f); vy = fmaxf(vy, 0.f); }
                long long oidx = rr * 128 + colb + nf * 8;
                if (mode == 1) {
                    __half2 h = __floats2half2_rn(vx, vy);
                    *(unsigned*)&Ch[oidx] = *(unsigned*)&h;
                } else {
                    *(float2*)&Cf[oidx] = make_float2(vx, vy);
                }
            }
        }
        __syncthreads();
        buf ^= 1;
    }
}

// agg + bias + relu: out[n] = relu(in[n] + sum_neigh in[j] + bias), fp16 io
__global__ void k_aggbr(const __half* __restrict__ in, __half* __restrict__ out,
                        const float* __restrict__ bias) {
    int node = (blockIdx.x * blockDim.x + threadIdx.x) >> 5;
    int lane = threadIdx.x & 31;
    if (node >= N_NODES) return;
    const uint2* in2 = (const uint2*)in;
    uint2 s = in2[(long long)node * 32 + lane];
    float2 p0 = __half22float2(*(__half2*)&s.x);
    float2 p1 = __half22float2(*(__half2*)&s.y);
    float a0 = p0.x, a1 = p0.y, a2 = p1.x, a3 = p1.y;
    int j = g_rowptr[node], end = g_rowptr[node + 1];
    for (; j + 4 <= end; j += 4) {
        int c0 = g_col[j], c1 = g_col[j + 1], c2 = g_col[j + 2], c3 = g_col[j + 3];
        uint2 v0 = in2[(long long)c0 * 32 + lane];
        uint2 v1 = in2[(long long)c1 * 32 + lane];
        uint2 v2 = in2[(long long)c2 * 32 + lane];
        uint2 v3 = in2[(long long)c3 * 32 + lane];
        float2 q;
        q = __half22float2(*(__half2*)&v0.x); a0 += q.x; a1 += q.y;
        q = __half22float2(*(__half2*)&v0.y); a2 += q.x; a3 += q.y;
        q = __half22float2(*(__half2*)&v1.x); a0 += q.x; a1 += q.y;
        q = __half22float2(*(__half2*)&v1.y); a2 += q.x; a3 += q.y;
        q = __half22float2(*(__half2*)&v2.x); a0 += q.x; a1 += q.y;
        q = __half22float2(*(__half2*)&v2.y); a2 += q.x; a3 += q.y;
        q = __half22float2(*(__half2*)&v3.x); a0 += q.x; a1 += q.y;
        q = __half22float2(*(__half2*)&v3.y); a2 += q.x; a3 += q.y;
    }
    for (; j < end; j++) {
        uint2 v = in2[(long long)g_col[j] * 32 + lane];
        float2 q0 = __half22float2(*(__half2*)&v.x);
        float2 q1 = __half22float2(*(__half2*)&v.y);
        a0 += q0.x; a1 += q0.y; a2 += q1.x; a3 += q1.y;
    }
    float4 b = *(const float4*)&bias[lane * 4];
    a0 = fmaxf(a0 + b.x, 0.f);
    a1 = fmaxf(a1 + b.y, 0.f);
    a2 = fmaxf(a2 + b.z, 0.f);
    a3 = fmaxf(a3 + b.w, 0.f);
    __half2 h0 = __floats2half2_rn(a0, a1);
    __half2 h1 = __floats2half2_rn(a2, a3);
    ((uint2*)out)[(long long)node * 32 + lane] = make_uint2(*(unsigned*)&h0, *(unsigned*)&h1);
}

// pool from fp16 (+ per-graph counts fused)
#define NODES_PER_BLK 128
__global__ void k_pool(const __half* __restrict__ h, const void* batch) {
    int wide = g_flag;
    int f = threadIdx.x;
    int base = blockIdx.x * NODES_PER_BLK;
    int end = base + NODES_PER_BLK;
    if (end > N_NODES) end = N_NODES;
    float run = 0.0f;
    int cur = -1, nrun = 0;
    for (int n = base; n < end; n++) {
        int g = (int)ld_idx(batch, n, wide);
        if (g != cur) {
            if (cur >= 0) {
                atomicAdd(&g_pooled[cur * D + f], run);
                if (f == 0) atomicAdd(&g_cnt[cur], nrun);
            }
            cur = g; run = 0.0f; nrun = 0;
        }
        run += __half2float(h[(long long)n * D + f]);
        nrun++;
    }
    if (cur >= 0) {
        atomicAdd(&g_pooled[cur * D + f], run);
        if (f == 0) atomicAdd(&g_cnt[cur], nrun);
    }
}

__global__ void k_final(const float* __restrict__ Wlin, const float* __restrict__ blin,
                        float* __restrict__ out) {
    int g = blockIdx.x;
    int k = threadIdx.x;
    float c = (float)g_cnt[g];
    if (c < 1.0f) c = 1.0f;
    float v = g_pooled[g * D + k] / c;
    __shared__ float red[128];
    for (int j = 0; j < NOUT; j++) {
        red[k] = v * Wlin[k * NOUT + j];
        __syncthreads();
        for (int s = 64; s > 0; s >>= 1) {
            if (k < s) red[k] += red[k + s];
            __syncthreads();
        }
        if (k == 0) out[g * NOUT + j] = red[0] + blin[j];
        __syncthreads();
    }
}

// ---------------- launch ------------------------------------------------------
extern "C" void kernel_launch(void* const* d_in, const int* in_sizes, int n_in,
                              void* d_out, int out_size) {
    const float* x    = (const float*)d_in[0];
    const void*  ei   = d_in[1];
    const void*  batch= d_in[2];
    const float* b1a  = (const float*)d_in[4];
    const float* b1b  = (const float*)d_in[6];
    const float* b2a  = (const float*)d_in[8];
    const float* b2b  = (const float*)d_in[10];
    const float* Wlin = (const float*)d_in[11];
    const float* blin = (const float*)d_in[12];
    float* out = (float*)d_out;

    __half *fA, *fB, *w16;
    cudaGetSymbolAddress((void**)&fA,  g_fA);
    cudaGetSymbolAddress((void**)&fB,  g_fB);
    cudaGetSymbolAddress((void**)&w16, g_W);

    static cudaStream_t s2;
    static cudaEvent_t e1, e2;
    static int inited = 0;
    if (!inited) {
        cudaStreamCreateWithFlags(&s2, cudaStreamNonBlocking);
        cudaEventCreateWithFlags(&e1, cudaEventDisableTiming);
        cudaEventCreateWithFlags(&e2, cudaEventDisableTiming);
        cudaFuncSetAttribute(k_gemm, cudaFuncAttributeMaxDynamicSharedMemorySize, SMEM_G);
        inited = 1;
    }

    const int aggBlocks = (N_NODES * 32 + 255) / 256;
    const int g4 = (NT + 3) / 4;   // 391

    k_zero_detect<<<448, 512>>>(ei);
    cudaEventRecord(e1, 0);

    // s0: wprep -> gemm1 (DRAM-bound: tpc=1, full grid for MLP)
    k_wprep<<<(4 * D * D + 255) / 256, 256>>>((const float*)d_in[3], (const float*)d_in[5],
                                              (const float*)d_in[7], (const float*)d_in[9]);
    // s2 (forked): CSR build
    cudaStreamWaitEvent(s2, e1, 0);
    k_hist<<<6250, 256, 0, s2>>>(ei);
    k_gemm<<<NT, 256, SMEM_G>>>(nullptr, x, w16, nullptr, fB, nullptr, 0, 1, 1, 1);  // u = x@W1a
    k_scan1<<<NB_SCAN, 1024, 0, s2>>>();
    k_scan3<<<NB_SCAN, 1024, 0, s2>>>();
    k_fill<<<6250, 256, 0, s2>>>(ei);
    cudaEventRecord(e2, s2);
    cudaStreamWaitEvent(0, e2, 0);

    // layer1: v = relu(u + agg(u) + b1a); h1 = relu(v@W1b + b1b)
    k_aggbr<<<aggBlocks, 256>>>(fB, fA, b1a);
    k_gemm<<<g4, 256, SMEM_G>>>(fA, nullptr, w16 + D * D, b1b, fB, nullptr, 1, 1, 0, 4);
    // layer2
    k_gemm<<<g4, 256, SMEM_G>>>(fB, nullptr, w16 + 2 * D * D, nullptr, fA, nullptr, 0, 1, 0, 4);
    k_aggbr<<<aggBlocks, 256>>>(fA, fB, b2a);
    k_gemm<<<g4, 256, SMEM_G>>>(fB, nullptr, w16 + 3 * D * D, b2b, fA, nullptr, 0, 1, 0, 4);
    // pool + classify (fp16 input)
    k_pool<<<(N_NODES + NODES_PER_BLK - 1) / NODES_PER_BLK, 128>>>(fA, batch);
    k_final<<<N_GRAPHS, 128>>>(Wlin, blin, out);
}

// round 12
// speedup vs baseline: 3.3337x; 1.0419x over previous
#include <cuda_runtime.h>
#include <cuda_fp16.h>
#include <cstdint>

#define N_NODES  100000
#define N_EDGES  1600000
#define N_GRAPHS 1000
#define D        128
#define NOUT     6
#define TILE_M   64
#define NT       1563              // ceil(100000/64)
#define NT_H0    782               // tiles in half0 -> rows [0, 50048)
#define HALF_N   50048
#define NB_SCAN  ((N_NODES + 1023) / 1024)   // 98

// ---------------- scratch ------------------------------------------------------
__device__ __align__(16) __half g_fA[N_NODES * D];
__device__ __align__(16) __half g_fB[N_NODES * D];
__device__ int   g_rowptr[N_NODES + 1];
__device__ int   g_pos[N_NODES];
__device__ int   g_col[N_EDGES];
__device__ int   g_bsum[NB_SCAN];
__device__ __align__(16) float g_pooled[N_GRAPHS * D];
__device__ int   g_cnt[N_GRAPHS];
__device__ int   g_flag;
__device__ __align__(16) __half g_W[4 * D * D];   // [k][n] fp16

__device__ __forceinline__ long long ld_idx(const void* p, long long i, int wide) {
    return wide ? ((const long long*)p)[i] : (long long)((const int*)p)[i];
}

__global__ void k_zero_detect(const void* ei) {
    int i = blockIdx.x * blockDim.x + threadIdx.x;
    if (blockIdx.x == 0 && threadIdx.x == 0) {
        const int* p = (const int*)ei;
        int wide = 1;
        for (int k = 0; k < 64; k++)
            if (p[2 * k + 1] != 0) { wide = 0; break; }
        g_flag = wide;
    }
    int total = N_NODES + N_GRAPHS * D + N_GRAPHS;
    for (; i < total; i += gridDim.x * blockDim.x) {
        if (i < N_NODES) g_pos[i] = 0;
        else if (i < N_NODES + N_GRAPHS * D) g_pooled[i - N_NODES] = 0.0f;
        else g_cnt[i - N_NODES - N_GRAPHS * D] = 0;
    }
}

__global__ void k_wprep(const float* __restrict__ Wa, const float* __restrict__ Wb,
                        const float* __restrict__ Wc, const float* __restrict__ Wd) {
    int idx = blockIdx.x * blockDim.x + threadIdx.x;
    if (idx >= 4 * D * D) return;
    int m = idx >> 14, j = idx & 16383;
    const float* W = (m == 0) ? Wa : (m == 1) ? Wb : (m == 2) ? Wc : Wd;
    g_W[idx] = __float2half_rn(W[j]);
}

__global__ void k_hist(const void* ei) {
    int wide = g_flag;
    int e = blockIdx.x * blockDim.x + threadIdx.x;
    for (; e < N_EDGES; e += gridDim.x * blockDim.x) {
        int dst = (int)ld_idx(ei, (long long)N_EDGES + e, wide);
        atomicAdd(&g_pos[dst], 1);
    }
}

__global__ void k_scan1() {
    __shared__ int s[1024];
    int t = threadIdx.x;
    int i = blockIdx.x * 1024 + t;
    int v = (i < N_NODES) ? g_pos[i] : 0;
    s[t] = v;
    __syncthreads();
    for (int off = 1; off < 1024; off <<= 1) {
        int x = (t >= off) ? s[t - off] : 0;
        __syncthreads();
        s[t] += x;
        __syncthreads();
    }
    if (i < N_NODES) g_rowptr[i + 1] = s[t];
    if (t == 1023) g_bsum[blockIdx.x] = s[1023];
}

__global__ void k_scan3() {
    __shared__ int soff;
    int t = threadIdx.x;
    if (t == 0) {
        int run = 0;
        for (int b = 0; b < (int)blockIdx.x; b++) run += g_bsum[b];
        soff = run;
    }
    __syncthreads();
    int off = soff;
    int i = blockIdx.x * 1024 + t;
    if (i < N_NODES) {
        int v = g_rowptr[i + 1] + off;
        g_rowptr[i + 1] = v;
        if (i + 1 < N_NODES) g_pos[i + 1] = v;
    }
    if (i == 0) { g_rowptr[0] = 0; g_pos[0] = 0; }
}

__global__ void k_fill(const void* ei) {
    int wide = g_flag;
    int e = blockIdx.x * blockDim.x + threadIdx.x;
    for (; e < N_EDGES; e += gridDim.x * blockDim.x) {
        int src = (int)ld_idx(ei, e, wide);
        int dst = (int)ld_idx(ei, (long long)N_EDGES + e, wide);
        int p = atomicAdd(&g_pos[dst], 1);
        g_col[p] = src;
    }
}

// ---------------- GEMM infra ---------------------------------------------------
#define LDB    136
#define A_SZ   8704

__device__ __forceinline__ uint32_t smem_u32(const void* p) {
    uint32_t a;
    asm("{ .reg .u64 t; cvta.to.shared.u64 t, %1; cvt.u32.u64 %0, t; }" : "=r"(a) : "l"(p));
    return a;
}
__device__ __forceinline__ void ldsm4(uint32_t& r0, uint32_t& r1, uint32_t& r2, uint32_t& r3, uint32_t addr) {
    asm volatile("ldmatrix.sync.aligned.m8n8.x4.shared.b16 {%0,%1,%2,%3}, [%4];"
                 : "=r"(r0), "=r"(r1), "=r"(r2), "=r"(r3) : "r"(addr));
}
__device__ __forceinline__ void ldsm4t(uint32_t& r0, uint32_t& r1, uint32_t& r2, uint32_t& r3, uint32_t addr) {
    asm volatile("ldmatrix.sync.aligned.m8n8.x4.trans.shared.b16 {%0,%1,%2,%3}, [%4];"
                 : "=r"(r0), "=r"(r1), "=r"(r2), "=r"(r3) : "r"(addr));
}
__device__ __forceinline__ void mma_f16(float* c, uint32_t a0, uint32_t a1, uint32_t a2, uint32_t a3,
                                        uint32_t b0, uint32_t b1) {
    asm volatile("mma.sync.aligned.m16n8k16.row.col.f32.f16.f16.f32 "
                 "{%0,%1,%2,%3}, {%4,%5,%6,%7}, {%8,%9}, {%0,%1,%2,%3};"
                 : "+f"(c[0]), "+f"(c[1]), "+f"(c[2]), "+f"(c[3])
                 : "r"(a0), "r"(a1), "r"(a2), "r"(a3), "r"(b0), "r"(b1));
}
__device__ __forceinline__ void cpa16(uint32_t dst, const void* src, int srcsize) {
    asm volatile("cp.async.cg.shared.global [%0], [%1], 16, %2;"
                 :: "r"(dst), "l"(src), "r"(srcsize));
}

__device__ __forceinline__ void stageA16(uint32_t sb, int base, int tile,
                                         const __half* __restrict__ Ain, int t) {
    const long long blockRow = (long long)tile * TILE_M;
#pragma unroll
    for (int i = 0; i < 4; i++) {
        int lin = t + i * 256;
        int row = lin >> 4, c = (lin & 15) * 8;
        long long gr = blockRow + row;
        int ok = (gr < N_NODES) ? 16 : 0;
        long long src = (gr < N_NODES) ? gr : 0;
        cpa16(sb + 2u * (base + row * LDB + c), Ain + src * 128 + c, ok);
    }
}

// ---------- single GEMM (used for gemm1 f32-in and gemm4 fp16-out) -------------
#define SMEM_G ((17408 + 2 * A_SZ) * 2)  // 69632

__global__ __launch_bounds__(256, 3)
void k_gemm(const __half* __restrict__ Ain, const float* __restrict__ Af32,
            const __half* __restrict__ W, const float* __restrict__ bias,
            __half* __restrict__ Ch,
            int doRelu, int inF32, int tpc, int tileBeg, int tileEnd) {
    extern __shared__ __half sm[];
    const int t = threadIdx.x;
    uint32_t sb = smem_u32(sm);
    const int SM_A0 = 17408;

#pragma unroll
    for (int i = 0; i < 8; i++) {
        int lin = t + i * 256;
        int row = lin >> 4, c = (lin & 15) * 8;
        cpa16(sb + 2u * (row * LDB + c), W + row * 128 + c, 16);
    }
    int tile0 = tileBeg + blockIdx.x * tpc;
    if (tile0 >= tileEnd) return;
    // stage first A
    if (inF32) {
        const long long blockRow = (long long)tile0 * TILE_M;
#pragma unroll
        for (int i = 0; i < 4; i++) {
            int lin = t + i * 256;
            int row = lin >> 4, c = (lin & 15) * 8;
            long long gr = blockRow + row;
            float4 v0 = make_float4(0.f, 0.f, 0.f, 0.f), v1 = v0;
            if (gr < N_NODES) {
                v0 = *(const float4*)&Af32[gr * 128 + c];
                v1 = *(const float4*)&Af32[gr * 128 + c + 4];
            }
            __half2 h0 = __floats2half2_rn(v0.x, v0.y);
            __half2 h1 = __floats2half2_rn(v0.z, v0.w);
            __half2 h2 = __floats2half2_rn(v1.x, v1.y);
            __half2 h3 = __floats2half2_rn(v1.z, v1.w);
            *(uint4*)&sm[SM_A0 + row * LDB + c] =
                make_uint4(*(unsigned*)&h0, *(unsigned*)&h1, *(unsigned*)&h2, *(unsigned*)&h3);
        }
    } else {
        stageA16(sb, SM_A0, tile0, Ain, t);
    }
    asm volatile("cp.async.commit_group;" ::: "memory");

    const int w = t >> 5, lane = t & 31;
    const int mbase = (w >> 1) * 16;
    const int nbase = (w & 1) * 64;
    const int lrow = lane & 15;
    const int lcol = (lane >> 4) * 8;
    const int colb = nbase + 2 * (lane & 3);

    float bx[8], by[8];
#pragma unroll
    for (int nf = 0; nf < 8; nf++) {
        bx[nf] = 0.f; by[nf] = 0.f;
        if (bias) { float2 bb = *(const float2*)&bias[colb + nf * 8]; bx[nf] = bb.x; by[nf] = bb.y; }
    }

    int buf = 0;
    for (int it = 0; it < tpc; it++) {
        int tile = tile0 + it;
        if (tile >= tileEnd) break;
        int havenext = (it + 1 < tpc) && (tile + 1 < tileEnd) && !inF32;
        if (havenext) stageA16(sb, SM_A0 + (buf ^ 1) * A_SZ, tile + 1, Ain, t);
        asm volatile("cp.async.commit_group;" ::: "memory");
        if (havenext) asm volatile("cp.async.wait_group 1;" ::: "memory");
        else          asm volatile("cp.async.wait_group 0;" ::: "memory");
        __syncthreads();

        float acc[8][4];
#pragma unroll
        for (int nf = 0; nf < 8; nf++)
#pragma unroll
            for (int r = 0; r < 4; r++) acc[nf][r] = 0.f;

        const int aBase = 17408 + buf * A_SZ;
#pragma unroll
        for (int kk = 0; kk < 8; kk++) {
            const int k0 = kk * 16;
            uint32_t a0, a1, a2, a3;
            ldsm4(a0, a1, a2, a3, sb + 2u * (aBase + (mbase + lrow) * LDB + k0 + lcol));
            uint32_t b[4][4];
#pragma unroll
            for (int ni = 0; ni < 4; ni++)
                ldsm4t(b[ni][0], b[ni][1], b[ni][2], b[ni][3],
                       sb + 2u * ((k0 + lrow) * LDB + nbase + ni * 16 + lcol));
#pragma unroll
            for (int ni = 0; ni < 4; ni++) {
                mma_f16(acc[2 * ni],     a0, a1, a2, a3, b[ni][0], b[ni][1]);
                mma_f16(acc[2 * ni + 1], a0, a1, a2, a3, b[ni][2], b[ni][3]);
            }
        }

        const long long r0 = (long long)tile * TILE_M + mbase + (lane >> 2);
#pragma unroll
        for (int nf = 0; nf < 8; nf++) {
#pragma unroll
            for (int half = 0; half < 2; half++) {
                long long rr = r0 + half * 8;
                if (rr >= N_NODES) continue;
                float vx = acc[nf][half * 2 + 0] + bx[nf];
                float vy = acc[nf][half * 2 + 1] + by[nf];
                if (doRelu) { vx = fmaxf(vx, 0.f); vy = fmaxf(vy, 0.f); }
                __half2 h = __floats2half2_rn(vx, vy);
                *(unsigned*)&Ch[rr * 128 + colb + nf * 8] = *(unsigned*)&h;
            }
        }
        __syncthreads();
        buf ^= 1;
    }
}

// ---------- fused double GEMM: p = relu(v@W1+b1) @ W2 --------------------------
#define SMEM_G2 ((2 * 17408 + 2 * A_SZ) * 2)   // 104448

__global__ __launch_bounds__(256, 2)
void k_gemm2x(const __half* __restrict__ Ain,
              const __half* __restrict__ W1, const __half* __restrict__ W2,
              const float* __restrict__ b1, __half* __restrict__ Cout,
              int tpc, int tileBeg, int tileEnd) {
    extern __shared__ __half sm[];
    const int t = threadIdx.x;
    uint32_t sb = smem_u32(sm);
    const int SM_W2 = 17408;
    const int SM_A0 = 2 * 17408;

#pragma unroll
    for (int i = 0; i < 8; i++) {
        int lin = t + i * 256;
        int row = lin >> 4, c = (lin & 15) * 8;
        cpa16(sb + 2u * (row * LDB + c),          W1 + row * 128 + c, 16);
        cpa16(sb + 2u * (SM_W2 + row * LDB + c),  W2 + row * 128 + c, 16);
    }
    int tile0 = tileBeg + blockIdx.x * tpc;
    if (tile0 >= tileEnd) return;
    stageA16(sb, SM_A0, tile0, Ain, t);
    asm volatile("cp.async.commit_group;" ::: "memory");

    const int w = t >> 5, lane = t & 31;
    const int mbase = (w >> 1) * 16;
    const int nbase = (w & 1) * 64;
    const int lrow = lane & 15;
    const int lcol = (lane >> 4) * 8;
    const int colb = nbase + 2 * (lane & 3);

    float bx[8], by[8];
#pragma unroll
    for (int nf = 0; nf < 8; nf++) {
        float2 bb = *(const float2*)&b1[colb + nf * 8];
        bx[nf] = bb.x; by[nf] = bb.y;
    }

    int buf = 0;
    for (int it = 0; it < tpc; it++) {
        int tile = tile0 + it;
        if (tile >= tileEnd) break;
        int havenext = (it + 1 < tpc) && (tile + 1 < tileEnd);
        if (havenext) stageA16(sb, SM_A0 + (buf ^ 1) * A_SZ, tile + 1, Ain, t);
        asm volatile("cp.async.commit_group;" ::: "memory");
        if (havenext) asm volatile("cp.async.wait_group 1;" ::: "memory");
        else          asm volatile("cp.async.wait_group 0;" ::: "memory");
        __syncthreads();

        const int aBase = SM_A0 + buf * A_SZ;
        float acc[8][4];

        // ---- pass 1: h = relu(v@W1 + b1) ----
#pragma unroll
        for (int nf = 0; nf < 8; nf++)
#pragma unroll
            for (int r = 0; r < 4; r++) acc[nf][r] = 0.f;
#pragma unroll
        for (int kk = 0; kk < 8; kk++) {
            const int k0 = kk * 16;
            uint32_t a0, a1, a2, a3;
            ldsm4(a0, a1, a2, a3, sb + 2u * (aBase + (mbase + lrow) * LDB + k0 + lcol));
            uint32_t b[4][4];
#pragma unroll
            for (int ni = 0; ni < 4; ni++)
                ldsm4t(b[ni][0], b[ni][1], b[ni][2], b[ni][3],
                       sb + 2u * ((k0 + lrow) * LDB + nbase + ni * 16 + lcol));
#pragma unroll
            for (int ni = 0; ni < 4; ni++) {
                mma_f16(acc[2 * ni],     a0, a1, a2, a3, b[ni][0], b[ni][1]);
                mma_f16(acc[2 * ni + 1], a0, a1, a2, a3, b[ni][2], b[ni][3]);
            }
        }
        __syncthreads();   // all pass-1 reads of A done before overwrite

        // write h into the consumed A buffer (fp16)
#pragma unroll
        for (int nf = 0; nf < 8; nf++) {
#pragma unroll
            for (int half = 0; half < 2; half++) {
                int row = mbase + (lane >> 2) + half * 8;
                float vx = fmaxf(acc[nf][half * 2 + 0] + bx[nf], 0.f);
                float vy = fmaxf(acc[nf][half * 2 + 1] + by[nf], 0.f);
                __half2 h = __floats2half2_rn(vx, vy);
                *(unsigned*)&sm[aBase + row * LDB + colb + nf * 8] = *(unsigned*)&h;
            }
        }
        __syncthreads();

        // ---- pass 2: p = h@W2 ----
#pragma unroll
        for (int nf = 0; nf < 8; nf++)
#pragma unroll
            for (int r = 0; r < 4; r++) acc[nf][r] = 0.f;
#pragma unroll
        for (int kk = 0; kk < 8; kk++) {
            const int k0 = kk * 16;
            uint32_t a0, a1, a2, a3;
            ldsm4(a0, a1, a2, a3, sb + 2u * (aBase + (mbase + lrow) * LDB + k0 + lcol));
            uint32_t b[4][4];
#pragma unroll
            for (int ni = 0; ni < 4; ni++)
                ldsm4t(b[ni][0], b[ni][1], b[ni][2], b[ni][3],
                       sb + 2u * (SM_W2 + (k0 + lrow) * LDB + nbase + ni * 16 + lcol));
#pragma unroll
            for (int ni = 0; ni < 4; ni++) {
                mma_f16(acc[2 * ni],     a0, a1, a2, a3, b[ni][0], b[ni][1]);
                mma_f16(acc[2 * ni + 1], a0, a1, a2, a3, b[ni][2], b[ni][3]);
            }
        }

        const long long r0 = (long long)tile * TILE_M + mbase + (lane >> 2);
#pragma unroll
        for (int nf = 0; nf < 8; nf++) {
#pragma unroll
            for (int half = 0; half < 2; half++) {
                long long rr = r0 + half * 8;
                if (rr >= N_NODES) continue;
                __half2 h = __floats2half2_rn(acc[nf][half * 2 + 0], acc[nf][half * 2 + 1]);
                *(unsigned*)&Cout[rr * 128 + colb + nf * 8] = *(unsigned*)&h;
            }
        }
        __syncthreads();
        buf ^= 1;
    }
}

// agg + bias + relu over node range [nodeBeg, nodeEnd)
__global__ void k_aggbr(const __half* __restrict__ in, __half* __restrict__ out,
                        const float* __restrict__ bias, int nodeBeg, int nodeEnd) {
    int node = nodeBeg + ((blockIdx.x * blockDim.x + threadIdx.x) >> 5);
    int lane = threadIdx.x & 31;
    if (node >= nodeEnd) return;
    const uint2* in2 = (const uint2*)in;
    uint2 s = in2[(long long)node * 32 + lane];
    float2 p0 = __half22float2(*(__half2*)&s.x);
    float2 p1 = __half22float2(*(__half2*)&s.y);
    float a0 = p0.x, a1 = p0.y, a2 = p1.x, a3 = p1.y;
    int j = g_rowptr[node], end = g_rowptr[node + 1];
    for (; j + 4 <= end; j += 4) {
        uint2 v0 = in2[(long long)g_col[j] * 32 + lane];
        uint2 v1 = in2[(long long)g_col[j + 1] * 32 + lane];
        uint2 v2 = in2[(long long)g_col[j + 2] * 32 + lane];
        uint2 v3 = in2[(long long)g_col[j + 3] * 32 + lane];
        float2 q;
        q = __half22float2(*(__half2*)&v0.x); a0 += q.x; a1 += q.y;
        q = __half22float2(*(__half2*)&v0.y); a2 += q.x; a3 += q.y;
        q = __half22float2(*(__half2*)&v1.x); a0 += q.x; a1 += q.y;
        q = __half22float2(*(__half2*)&v1.y); a2 += q.x; a3 += q.y;
        q = __half22float2(*(__half2*)&v2.x); a0 += q.x; a1 += q.y;
        q = __half22float2(*(__half2*)&v2.y); a2 += q.x; a3 += q.y;
        q = __half22float2(*(__half2*)&v3.x); a0 += q.x; a1 += q.y;
        q = __half22float2(*(__half2*)&v3.y); a2 += q.x; a3 += q.y;
    }
    for (; j < end; j++) {
        uint2 v = in2[(long long)g_col[j] * 32 + lane];
        float2 q0 = __half22float2(*(__half2*)&v.x);
        float2 q1 = __half22float2(*(__half2*)&v.y);
        a0 += q0.x; a1 += q0.y; a2 += q1.x; a3 += q1.y;
    }
    float4 b = *(const float4*)&bias[lane * 4];
    a0 = fmaxf(a0 + b.x, 0.f);
    a1 = fmaxf(a1 + b.y, 0.f);
    a2 = fmaxf(a2 + b.z, 0.f);
    a3 = fmaxf(a3 + b.w, 0.f);
    __half2 h0 = __floats2half2_rn(a0, a1);
    __half2 h1 = __floats2half2_rn(a2, a3);
    ((uint2*)out)[(long long)node * 32 + lane] = make_uint2(*(unsigned*)&h0, *(unsigned*)&h1);
}

// pool over node range
#define NODES_PER_BLK 128
__global__ void k_pool(const __half* __restrict__ h, const void* batch,
                       int nodeBeg, int nodeEnd) {
    int wide = g_flag;
    int f = threadIdx.x;
    int base = nodeBeg + blockIdx.x * NODES_PER_BLK;
    int end = base + NODES_PER_BLK;
    if (end > nodeEnd) end = nodeEnd;
    if (base >= nodeEnd) return;
    float run = 0.0f;
    int cur = -1, nrun = 0;
    for (int n = base; n < end; n++) {
        int g = (int)ld_idx(batch, n, wide);
        if (g != cur) {
            if (cur >= 0) {
                atomicAdd(&g_pooled[cur * D + f], run);
                if (f == 0) atomicAdd(&g_cnt[cur], nrun);
            }
            cur = g; run = 0.0f; nrun = 0;
        }
        run += __half2float(h[(long long)n * D + f]);
        nrun++;
    }
    if (cur >= 0) {
        atomicAdd(&g_pooled[cur * D + f], run);
        if (f == 0) atomicAdd(&g_cnt[cur], nrun);
    }
}

__global__ void k_final(const float* __restrict__ Wlin, const float* __restrict__ blin,
                        float* __restrict__ out) {
    int g = blockIdx.x;
    int k = threadIdx.x;
    float c = (float)g_cnt[g];
    if (c < 1.0f) c = 1.0f;
    float v = g_pooled[g * D + k] / c;
    __shared__ float red[128];
    for (int j = 0; j < NOUT; j++) {
        red[k] = v * Wlin[k * NOUT + j];
        __syncthreads();
        for (int s = 64; s > 0; s >>= 1) {
            if (k < s) red[k] += red[k + s];
            __syncthreads();
        }
        if (k == 0) out[g * NOUT + j] = red[0] + blin[j];
        __syncthreads();
    }
}

// ---------------- launch ------------------------------------------------------
extern "C" void kernel_launch(void* const* d_in, const int* in_sizes, int n_in,
                              void* d_out, int out_size) {
    const float* x    = (const float*)d_in[0];
    const void*  ei   = d_in[1];
    const void*  batch= d_in[2];
    const float* b1a  = (const float*)d_in[4];
    const float* b1b  = (const float*)d_in[6];
    const float* b2a  = (const float*)d_in[8];
    const float* b2b  = (const float*)d_in[10];
    const float* Wlin = (const float*)d_in[11];
    const float* blin = (const float*)d_in[12];
    float* out = (float*)d_out;

    __half *fA, *fB, *w16;
    cudaGetSymbolAddress((void**)&fA,  g_fA);
    cudaGetSymbolAddress((void**)&fB,  g_fB);
    cudaGetSymbolAddress((void**)&w16, g_W);

    static cudaStream_t s2;
    static cudaEvent_t e1, e2, e3, e6, e7, e8;
    static int inited = 0;
    if (!inited) {
        cudaStreamCreateWithFlags(&s2, cudaStreamNonBlocking);
        cudaEventCreateWithFlags(&e1, cudaEventDisableTiming);
        cudaEventCreateWithFlags(&e2, cudaEventDisableTiming);
        cudaEventCreateWithFlags(&e3, cudaEventDisableTiming);
        cudaEventCreateWithFlags(&e6, cudaEventDisableTiming);
        cudaEventCreateWithFlags(&e7, cudaEventDisableTiming);
        cudaEventCreateWithFlags(&e8, cudaEventDisableTiming);
        cudaFuncSetAttribute(k_gemm,   cudaFuncAttributeMaxDynamicSharedMemorySize, SMEM_G);
        cudaFuncSetAttribute(k_gemm2x, cudaFuncAttributeMaxDynamicSharedMemorySize, SMEM_G2);
        inited = 1;
    }

    const int aggB0 = (HALF_N * 32 + 255) / 256;                 // 6256
    const int aggB1 = ((N_NODES - HALF_N) * 32 + 255) / 256;     // 6244
    const int poolB0 = (HALF_N + NODES_PER_BLK - 1) / NODES_PER_BLK;
    const int poolB1 = (N_NODES - HALF_N + NODES_PER_BLK - 1) / NODES_PER_BLK;
    const int g2x0 = (NT_H0 + 3) / 4;            // 196
    const int g2x1 = (NT - NT_H0 + 3) / 4;       // 196

    k_zero_detect<<<448, 512>>>(ei);
    cudaEventRecord(e1, 0);

    // s0: wprep -> gemm1 (full, DRAM-bound, tpc=1)
    k_wprep<<<(4 * D * D + 255) / 256, 256>>>((const float*)d_in[3], (const float*)d_in[5],
                                              (const float*)d_in[7], (const float*)d_in[9]);
    // s2: CSR build
    cudaStreamWaitEvent(s2, e1, 0);
    k_hist<<<6250, 256, 0, s2>>>(ei);
    k_gemm<<<NT, 256, SMEM_G>>>(nullptr, x, w16, nullptr, fB, 0, 1, 1, 0, NT);  // u
    cudaEventRecord(e3, 0);
    k_scan1<<<NB_SCAN, 1024, 0, s2>>>();
    k_scan3<<<NB_SCAN, 1024, 0, s2>>>();
    k_fill<<<6250, 256, 0, s2>>>(ei);
    cudaEventRecord(e2, s2);

    // agg1 halves: s0 h0 (needs fill), s2 h1 (needs gemm1)
    cudaStreamWaitEvent(0, e2, 0);
    cudaStreamWaitEvent(s2, e3, 0);
    k_aggbr<<<aggB0, 256>>>(fB, fA, b1a, 0, HALF_N);
    k_aggbr<<<aggB1, 256, 0, s2>>>(fB, fA, b1a, HALF_N, N_NODES);

    // fused gemm2+3 halves (h1 = relu(v@W1b+b1b); p = h1@W2a)
    k_gemm2x<<<g2x0, 256, SMEM_G2>>>(fA, w16 + D * D, w16 + 2 * D * D, b1b, fB, 4, 0, NT_H0);
    cudaEventRecord(e7, 0);
    k_gemm2x<<<g2x1, 256, SMEM_G2, s2>>>(fA, w16 + D * D, w16 + 2 * D * D, b1b, fB, 4, NT_H0, NT);
    cudaEventRecord(e6, s2);

    // agg2 halves (each needs BOTH p halves)
    cudaStreamWaitEvent(0, e6, 0);
    cudaStreamWaitEvent(s2, e7, 0);
    k_aggbr<<<aggB0, 256>>>(fB, fA, b2a, 0, HALF_N);
    k_aggbr<<<aggB1, 256, 0, s2>>>(fB, fA, b2a, HALF_N, N_NODES);

    // gemm4 halves (r = q@W2b + b2b, fp16 out) + pool halves
    k_gemm<<<g2x0, 256, SMEM_G>>>(fA, nullptr, w16 + 3 * D * D, b2b, fB, 0, 0, 4, 0, NT_H0);
    k_gemm<<<g2x1, 256, SMEM_G, s2>>>(fA, nullptr, w16 + 3 * D * D, b2b, fB, 0, 0, 4, NT_H0, NT);
    k_pool<<<poolB0, 128>>>(fB, batch, 0, HALF_N);
    k_pool<<<poolB1, 128, 0, s2>>>(fB, batch, HALF_N, N_NODES);
    cudaEventRecord(e8, s2);
    cudaStreamWaitEvent(0, e8, 0);
    k_final<<<N_GRAPHS, 128>>>(Wlin, blin, out);
}

// round 13
// speedup vs baseline: 3.5419x; 1.0624x over previous
#include <cuda_runtime.h>
#include <cuda_fp16.h>
#include <cstdint>

#define N_NODES  100000
#define N_EDGES  1600000
#define N_GRAPHS 1000
#define D        128
#define NOUT     6
#define TILE_M   64
#define NT       1563
#define NT_H0    782
#define HALF_N   50048
#define NB_SCAN  ((N_NODES + 1023) / 1024)   // 98

// ---------------- scratch ------------------------------------------------------
__device__ __align__(16) __half g_fA[N_NODES * D];
__device__ __align__(16) __half g_fB[N_NODES * D];
__device__ int   g_rowptr[N_NODES + 1];
__device__ int   g_pos[N_NODES];
__device__ int   g_col[N_EDGES];
__device__ unsigned long long g_scanpub[NB_SCAN];
__device__ __align__(16) float g_pooled[N_GRAPHS * D];
__device__ int   g_cnt[N_GRAPHS];
__device__ int   g_flag;
__device__ __align__(16) __half g_W[4 * D * D];   // [k][n] fp16

__device__ __forceinline__ long long ld_idx(const void* p, long long i, int wide) {
    return wide ? ((const long long*)p)[i] : (long long)((const int*)p)[i];
}

// zero CSR-critical state + dtype detect
__global__ void k_zero1(const void* ei) {
    int i = blockIdx.x * blockDim.x + threadIdx.x;
    if (blockIdx.x == 0 && threadIdx.x == 0) {
        const int* p = (const int*)ei;
        int wide = 1;
        for (int k = 0; k < 64; k++)
            if (p[2 * k + 1] != 0) { wide = 0; break; }
        g_flag = wide;
    }
    for (; i < N_NODES + NB_SCAN; i += gridDim.x * blockDim.x) {
        if (i < N_NODES) g_pos[i] = 0;
        else g_scanpub[i - N_NODES] = 0ULL;
    }
}

// zero pool state (off critical path)
__global__ void k_zero2() {
    int i = blockIdx.x * blockDim.x + threadIdx.x;
    for (; i < N_GRAPHS * D + N_GRAPHS; i += gridDim.x * blockDim.x) {
        if (i < N_GRAPHS * D) g_pooled[i] = 0.0f;
        else g_cnt[i - N_GRAPHS * D] = 0;
    }
}

__global__ void k_wprep(const float* __restrict__ Wa, const float* __restrict__ Wb,
                        const float* __restrict__ Wc, const float* __restrict__ Wd) {
    int idx = blockIdx.x * blockDim.x + threadIdx.x;
    if (idx >= 4 * D * D) return;
    int m = idx >> 14, j = idx & 16383;
    const float* W = (m == 0) ? Wa : (m == 1) ? Wb : (m == 2) ? Wc : Wd;
    g_W[idx] = __float2half_rn(W[j]);
}

__global__ void k_hist(const void* ei) {
    int wide = g_flag;
    int e = blockIdx.x * blockDim.x + threadIdx.x;
    for (; e < N_EDGES; e += gridDim.x * blockDim.x) {
        int dst = (int)ld_idx(ei, (long long)N_EDGES + e, wide);
        atomicAdd(&g_pos[dst], 1);
    }
}

// single-kernel scan (decoupled aggregate lookback; 98 blocks, all resident)
__global__ void k_scanlb() {
    __shared__ int s[1024];
    __shared__ int r[1024];
    int t = threadIdx.x, bid = blockIdx.x;
    int i = bid * 1024 + t;
    int v = (i < N_NODES) ? g_pos[i] : 0;
    s[t] = v;
    __syncthreads();
    for (int off = 1; off < 1024; off <<= 1) {
        int x = (t >= off) ? s[t - off] : 0;
        __syncthreads();
        s[t] += x;
        __syncthreads();
    }
    if (t == 1023)
        atomicExch(&g_scanpub[bid], 0x8000000000000000ULL | (unsigned long long)(unsigned)s[1023]);
    // lookback: thread t spin-reads predecessor t's aggregate
    int myagg = 0;
    if (t < bid) {
        unsigned long long pv;
        do { pv = atomicAdd(&g_scanpub[t], 0ULL); } while (pv == 0ULL);
        myagg = (int)(pv & 0xffffffffu);
    }
    r[t] = myagg;
    __syncthreads();
    for (int off = 512; off > 0; off >>= 1) {
        if (t < off) r[t] += r[t + off];
        __syncthreads();
    }
    int off = r[0];
    if (i < N_NODES) {
        int inc = s[t] + off;        // inclusive prefix at i
        g_rowptr[i + 1] = inc;
        g_pos[i] = inc - v;          // exclusive prefix = fill cursor
    }
    if (i == 0) g_rowptr[0] = 0;
}

__global__ void k_fill(const void* ei) {
    int wide = g_flag;
    int e = blockIdx.x * blockDim.x + threadIdx.x;
    for (; e < N_EDGES; e += gridDim.x * blockDim.x) {
        int src = (int)ld_idx(ei, e, wide);
        int dst = (int)ld_idx(ei, (long long)N_EDGES + e, wide);
        int p = atomicAdd(&g_pos[dst], 1);
        g_col[p] = src;
    }
}

// ---------------- GEMM infra ---------------------------------------------------
#define LDB    136
#define A_SZ   8704

__device__ __forceinline__ uint32_t smem_u32(const void* p) {
    uint32_t a;
    asm("{ .reg .u64 t; cvta.to.shared.u64 t, %1; cvt.u32.u64 %0, t; }" : "=r"(a) : "l"(p));
    return a;
}
__device__ __forceinline__ void ldsm4(uint32_t& r0, uint32_t& r1, uint32_t& r2, uint32_t& r3, uint32_t addr) {
    asm volatile("ldmatrix.sync.aligned.m8n8.x4.shared.b16 {%0,%1,%2,%3}, [%4];"
                 : "=r"(r0), "=r"(r1), "=r"(r2), "=r"(r3) : "r"(addr));
}
__device__ __forceinline__ void ldsm4t(uint32_t& r0, uint32_t& r1, uint32_t& r2, uint32_t& r3, uint32_t addr) {
    asm volatile("ldmatrix.sync.aligned.m8n8.x4.trans.shared.b16 {%0,%1,%2,%3}, [%4];"
                 : "=r"(r0), "=r"(r1), "=r"(r2), "=r"(r3) : "r"(addr));
}
__device__ __forceinline__ void mma_f16(float* c, uint32_t a0, uint32_t a1, uint32_t a2, uint32_t a3,
                                        uint32_t b0, uint32_t b1) {
    asm volatile("mma.sync.aligned.m16n8k16.row.col.f32.f16.f16.f32 "
                 "{%0,%1,%2,%3}, {%4,%5,%6,%7}, {%8,%9}, {%0,%1,%2,%3};"
                 : "+f"(c[0]), "+f"(c[1]), "+f"(c[2]), "+f"(c[3])
                 : "r"(a0), "r"(a1), "r"(a2), "r"(a3), "r"(b0), "r"(b1));
}
__device__ __forceinline__ void cpa16(uint32_t dst, const void* src, int srcsize) {
    asm volatile("cp.async.cg.shared.global [%0], [%1], 16, %2;"
                 :: "r"(dst), "l"(src), "r"(srcsize));
}

__device__ __forceinline__ void stageA16(uint32_t sb, int base, int tile,
                                         const __half* __restrict__ Ain, int t) {
    const long long blockRow = (long long)tile * TILE_M;
#pragma unroll
    for (int i = 0; i < 4; i++) {
        int lin = t + i * 256;
        int row = lin >> 4, c = (lin & 15) * 8;
        long long gr = blockRow + row;
        int ok = (gr < N_NODES) ? 16 : 0;
        long long src = (gr < N_NODES) ? gr : 0;
        cpa16(sb + 2u * (base + row * LDB + c), Ain + src * 128 + c, ok);
    }
}

#define SMEM_G ((17408 + 2 * A_SZ) * 2)  // 69632

__global__ __launch_bounds__(256, 3)
void k_gemm(const __half* __restrict__ Ain, const float* __restrict__ Af32,
            const __half* __restrict__ W, const float* __restrict__ bias,
            __half* __restrict__ Ch,
            int doRelu, int inF32, int tpc, int tileBeg, int tileEnd) {
    extern __shared__ __half sm[];
    const int t = threadIdx.x;
    uint32_t sb = smem_u32(sm);
    const int SM_A0 = 17408;

#pragma unroll
    for (int i = 0; i < 8; i++) {
        int lin = t + i * 256;
        int row = lin >> 4, c = (lin & 15) * 8;
        cpa16(sb + 2u * (row * LDB + c), W + row * 128 + c, 16);
    }
    int tile0 = tileBeg + blockIdx.x * tpc;
    if (tile0 >= tileEnd) return;
    if (inF32) {
        const long long blockRow = (long long)tile0 * TILE_M;
#pragma unroll
        for (int i = 0; i < 4; i++) {
            int lin = t + i * 256;
            int row = lin >> 4, c = (lin & 15) * 8;
            long long gr = blockRow + row;
            float4 v0 = make_float4(0.f, 0.f, 0.f, 0.f), v1 = v0;
            if (gr < N_NODES) {
                v0 = *(const float4*)&Af32[gr * 128 + c];
                v1 = *(const float4*)&Af32[gr * 128 + c + 4];
            }
            __half2 h0 = __floats2half2_rn(v0.x, v0.y);
            __half2 h1 = __floats2half2_rn(v0.z, v0.w);
            __half2 h2 = __floats2half2_rn(v1.x, v1.y);
            __half2 h3 = __floats2half2_rn(v1.z, v1.w);
            *(uint4*)&sm[SM_A0 + row * LDB + c] =
                make_uint4(*(unsigned*)&h0, *(unsigned*)&h1, *(unsigned*)&h2, *(unsigned*)&h3);
        }
    } else {
        stageA16(sb, SM_A0, tile0, Ain, t);
    }
    asm volatile("cp.async.commit_group;" ::: "memory");

    const int w = t >> 5, lane = t & 31;
    const int mbase = (w >> 1) * 16;
    const int nbase = (w & 1) * 64;
    const int lrow = lane & 15;
    const int lcol = (lane >> 4) * 8;
    const int colb = nbase + 2 * (lane & 3);

    float bx[8], by[8];
#pragma unroll
    for (int nf = 0; nf < 8; nf++) {
        bx[nf] = 0.f; by[nf] = 0.f;
        if (bias) { float2 bb = *(const float2*)&bias[colb + nf * 8]; bx[nf] = bb.x; by[nf] = bb.y; }
    }

    int buf = 0;
    for (int it = 0; it < tpc; it++) {
        int tile = tile0 + it;
        if (tile >= tileEnd) break;
        int havenext = (it + 1 < tpc) && (tile + 1 < tileEnd) && !inF32;
        if (havenext) stageA16(sb, SM_A0 + (buf ^ 1) * A_SZ, tile + 1, Ain, t);
        asm volatile("cp.async.commit_group;" ::: "memory");
        if (havenext) asm volatile("cp.async.wait_group 1;" ::: "memory");
        else          asm volatile("cp.async.wait_group 0;" ::: "memory");
        __syncthreads();

        float acc[8][4];
#pragma unroll
        for (int nf = 0; nf < 8; nf++)
#pragma unroll
            for (int r = 0; r < 4; r++) acc[nf][r] = 0.f;

        const int aBase = 17408 + buf * A_SZ;
#pragma unroll
        for (int kk = 0; kk < 8; kk++) {
            const int k0 = kk * 16;
            uint32_t a0, a1, a2, a3;
            ldsm4(a0, a1, a2, a3, sb + 2u * (aBase + (mbase + lrow) * LDB + k0 + lcol));
            uint32_t b[4][4];
#pragma unroll
            for (int ni = 0; ni < 4; ni++)
                ldsm4t(b[ni][0], b[ni][1], b[ni][2], b[ni][3],
                       sb + 2u * ((k0 + lrow) * LDB + nbase + ni * 16 + lcol));
#pragma unroll
            for (int ni = 0; ni < 4; ni++) {
                mma_f16(acc[2 * ni],     a0, a1, a2, a3, b[ni][0], b[ni][1]);
                mma_f16(acc[2 * ni + 1], a0, a1, a2, a3, b[ni][2], b[ni][3]);
            }
        }

        const long long r0 = (long long)tile * TILE_M + mbase + (lane >> 2);
#pragma unroll
        for (int nf = 0; nf < 8; nf++) {
#pragma unroll
            for (int half = 0; half < 2; half++) {
                long long rr = r0 + half * 8;
                if (rr >= N_NODES) continue;
                float vx = acc[nf][half * 2 + 0] + bx[nf];
                float vy = acc[nf][half * 2 + 1] + by[nf];
                if (doRelu) { vx = fmaxf(vx, 0.f); vy = fmaxf(vy, 0.f); }
                __half2 h = __floats2half2_rn(vx, vy);
                *(unsigned*)&Ch[rr * 128 + colb + nf * 8] = *(unsigned*)&h;
            }
        }
        __syncthreads();
        buf ^= 1;
    }
}

// ---------- fused double GEMM --------------------------------------------------
#define SMEM_G2 ((2 * 17408 + 2 * A_SZ) * 2)   // 104448

__global__ __launch_bounds__(256, 2)
void k_gemm2x(const __half* __restrict__ Ain,
              const __half* __restrict__ W1, const __half* __restrict__ W2,
              const float* __restrict__ b1, __half* __restrict__ Cout,
              int tpc, int tileBeg, int tileEnd) {
    extern __shared__ __half sm[];
    const int t = threadIdx.x;
    uint32_t sb = smem_u32(sm);
    const int SM_W2 = 17408;
    const int SM_A0 = 2 * 17408;

#pragma unroll
    for (int i = 0; i < 8; i++) {
        int lin = t + i * 256;
        int row = lin >> 4, c = (lin & 15) * 8;
        cpa16(sb + 2u * (row * LDB + c),          W1 + row * 128 + c, 16);
        cpa16(sb + 2u * (SM_W2 + row * LDB + c),  W2 + row * 128 + c, 16);
    }
    int tile0 = tileBeg + blockIdx.x * tpc;
    if (tile0 >= tileEnd) return;
    stageA16(sb, SM_A0, tile0, Ain, t);
    asm volatile("cp.async.commit_group;" ::: "memory");

    const int w = t >> 5, lane = t & 31;
    const int mbase = (w >> 1) * 16;
    const int nbase = (w & 1) * 64;
    const int lrow = lane & 15;
    const int lcol = (lane >> 4) * 8;
    const int colb = nbase + 2 * (lane & 3);

    float bx[8], by[8];
#pragma unroll
    for (int nf = 0; nf < 8; nf++) {
        float2 bb = *(const float2*)&b1[colb + nf * 8];
        bx[nf] = bb.x; by[nf] = bb.y;
    }

    int buf = 0;
    for (int it = 0; it < tpc; it++) {
        int tile = tile0 + it;
        if (tile >= tileEnd) break;
        int havenext = (it + 1 < tpc) && (tile + 1 < tileEnd);
        if (havenext) stageA16(sb, SM_A0 + (buf ^ 1) * A_SZ, tile + 1, Ain, t);
        asm volatile("cp.async.commit_group;" ::: "memory");
        if (havenext) asm volatile("cp.async.wait_group 1;" ::: "memory");
        else          asm volatile("cp.async.wait_group 0;" ::: "memory");
        __syncthreads();

        const int aBase = SM_A0 + buf * A_SZ;
        float acc[8][4];

        // pass 1: h = relu(v@W1 + b1)
#pragma unroll
        for (int nf = 0; nf < 8; nf++)
#pragma unroll
            for (int r = 0; r < 4; r++) acc[nf][r] = 0.f;
#pragma unroll
        for (int kk = 0; kk < 8; kk++) {
            const int k0 = kk * 16;
            uint32_t a0, a1, a2, a3;
            ldsm4(a0, a1, a2, a3, sb + 2u * (aBase + (mbase + lrow) * LDB + k0 + lcol));
            uint32_t b[4][4];
#pragma unroll
            for (int ni = 0; ni < 4; ni++)
                ldsm4t(b[ni][0], b[ni][1], b[ni][2], b[ni][3],
                       sb + 2u * ((k0 + lrow) * LDB + nbase + ni * 16 + lcol));
#pragma unroll
            for (int ni = 0; ni < 4; ni++) {
                mma_f16(acc[2 * ni],     a0, a1, a2, a3, b[ni][0], b[ni][1]);
                mma_f16(acc[2 * ni + 1], a0, a1, a2, a3, b[ni][2], b[ni][3]);
            }
        }
        __syncthreads();

#pragma unroll
        for (int nf = 0; nf < 8; nf++) {
#pragma unroll
            for (int half = 0; half < 2; half++) {
                int row = mbase + (lane >> 2) + half * 8;
                float vx = fmaxf(acc[nf][half * 2 + 0] + bx[nf], 0.f);
                float vy = fmaxf(acc[nf][half * 2 + 1] + by[nf], 0.f);
                __half2 h = __floats2half2_rn(vx, vy);
                *(unsigned*)&sm[aBase + row * LDB + colb + nf * 8] = *(unsigned*)&h;
            }
        }
        __syncthreads();

        // pass 2: p = h@W2
#pragma unroll
        for (int nf = 0; nf < 8; nf++)
#pragma unroll
            for (int r = 0; r < 4; r++) acc[nf][r] = 0.f;
#pragma unroll
        for (int kk = 0; kk < 8; kk++) {
            const int k0 = kk * 16;
            uint32_t a0, a1, a2, a3;
            ldsm4(a0, a1, a2, a3, sb + 2u * (aBase + (mbase + lrow) * LDB + k0 + lcol));
            uint32_t b[4][4];
#pragma unroll
            for (int ni = 0; ni < 4; ni++)
                ldsm4t(b[ni][0], b[ni][1], b[ni][2], b[ni][3],
                       sb + 2u * (SM_W2 + (k0 + lrow) * LDB + nbase + ni * 16 + lcol));
#pragma unroll
            for (int ni = 0; ni < 4; ni++) {
                mma_f16(acc[2 * ni],     a0, a1, a2, a3, b[ni][0], b[ni][1]);
                mma_f16(acc[2 * ni + 1], a0, a1, a2, a3, b[ni][2], b[ni][3]);
            }
        }

        const long long r0 = (long long)tile * TILE_M + mbase + (lane >> 2);
#pragma unroll
        for (int nf = 0; nf < 8; nf++) {
#pragma unroll
            for (int half = 0; half < 2; half++) {
                long long rr = r0 + half * 8;
                if (rr >= N_NODES) continue;
                __half2 h = __floats2half2_rn(acc[nf][half * 2 + 0], acc[nf][half * 2 + 1]);
                *(unsigned*)&Cout[rr * 128 + colb + nf * 8] = *(unsigned*)&h;
            }
        }
        __syncthreads();
        buf ^= 1;
    }
}

// agg + bias + relu: 2 nodes per warp, uint4 lanes (16 lanes x 16B per row)
__device__ __forceinline__ void addrow(float* a, uint4 v) {
    __half2* hp = (__half2*)&v;
#pragma unroll
    for (int q = 0; q < 4; q++) {
        float2 f = __half22float2(hp[q]);
        a[2 * q] += f.x; a[2 * q + 1] += f.y;
    }
}

__global__ void k_aggbr(const __half* __restrict__ in, __half* __restrict__ out,
                        const float* __restrict__ bias, int nodeBeg, int nodeEnd) {
    int gwarp = (blockIdx.x * blockDim.x + threadIdx.x) >> 5;
    int halfid = (threadIdx.x >> 4) & 1;
    int l16 = threadIdx.x & 15;
    int node = nodeBeg + gwarp * 2 + halfid;
    if (node >= nodeEnd) return;
    const uint4* in4 = (const uint4*)in;
    float a[8];
    {
        uint4 sv = in4[(long long)node * 16 + l16];
        __half2* hp = (__half2*)&sv;
#pragma unroll
        for (int q = 0; q < 4; q++) {
            float2 f = __half22float2(hp[q]);
            a[2 * q] = f.x; a[2 * q + 1] = f.y;
        }
    }
    int j = g_rowptr[node], end = g_rowptr[node + 1];
    for (; j + 4 <= end; j += 4) {
        int c0 = g_col[j], c1 = g_col[j + 1], c2 = g_col[j + 2], c3 = g_col[j + 3];
        uint4 v0 = in4[(long long)c0 * 16 + l16];
        uint4 v1 = in4[(long long)c1 * 16 + l16];
        uint4 v2 = in4[(long long)c2 * 16 + l16];
        uint4 v3 = in4[(long long)c3 * 16 + l16];
        addrow(a, v0); addrow(a, v1); addrow(a, v2); addrow(a, v3);
    }
    for (; j < end; j++) {
        uint4 v = in4[(long long)g_col[j] * 16 + l16];
        addrow(a, v);
    }
    float4 b0 = *(const float4*)&bias[l16 * 8];
    float4 b1 = *(const float4*)&bias[l16 * 8 + 4];
    a[0] = fmaxf(a[0] + b0.x, 0.f); a[1] = fmaxf(a[1] + b0.y, 0.f);
    a[2] = fmaxf(a[2] + b0.z, 0.f); a[3] = fmaxf(a[3] + b0.w, 0.f);
    a[4] = fmaxf(a[4] + b1.x, 0.f); a[5] = fmaxf(a[5] + b1.y, 0.f);
    a[6] = fmaxf(a[6] + b1.z, 0.f); a[7] = fmaxf(a[7] + b1.w, 0.f);
    __half2 h0 = __floats2half2_rn(a[0], a[1]);
    __half2 h1 = __floats2half2_rn(a[2], a[3]);
    __half2 h2 = __floats2half2_rn(a[4], a[5]);
    __half2 h3 = __floats2half2_rn(a[6], a[7]);
    ((uint4*)out)[(long long)node * 16 + l16] =
        make_uint4(*(unsigned*)&h0, *(unsigned*)&h1, *(unsigned*)&h2, *(unsigned*)&h3);
}

// pool over node range
#define NODES_PER_BLK 128
__global__ void k_pool(const __half* __restrict__ h, const void* batch,
                       int nodeBeg, int nodeEnd) {
    int wide = g_flag;
    int f = threadIdx.x;
    int base = nodeBeg + blockIdx.x * NODES_PER_BLK;
    int end = base + NODES_PER_BLK;
    if (end > nodeEnd) end = nodeEnd;
    if (base >= nodeEnd) return;
    float run = 0.0f;
    int cur = -1, nrun = 0;
    for (int n = base; n < end; n++) {
        int g = (int)ld_idx(batch, n, wide);
        if (g != cur) {
            if (cur >= 0) {
                atomicAdd(&g_pooled[cur * D + f], run);
                if (f == 0) atomicAdd(&g_cnt[cur], nrun);
            }
            cur = g; run = 0.0f; nrun = 0;
        }
        run += __half2float(h[(long long)n * D + f]);
        nrun++;
    }
    if (cur >= 0) {
        atomicAdd(&g_pooled[cur * D + f], run);
        if (f == 0) atomicAdd(&g_cnt[cur], nrun);
    }
}

__global__ void k_final(const float* __restrict__ Wlin, const float* __restrict__ blin,
                        float* __restrict__ out) {
    int g = blockIdx.x;
    int k = threadIdx.x;
    float c = (float)g_cnt[g];
    if (c < 1.0f) c = 1.0f;
    float v = g_pooled[g * D + k] / c;
    __shared__ float red[128];
    for (int j = 0; j < NOUT; j++) {
        red[k] = v * Wlin[k * NOUT + j];
        __syncthreads();
        for (int s = 64; s > 0; s >>= 1) {
            if (k < s) red[k] += red[k + s];
            __syncthreads();
        }
        if (k == 0) out[g * NOUT + j] = red[0] + blin[j];
        __syncthreads();
    }
}

// ---------------- launch ------------------------------------------------------
extern "C" void kernel_launch(void* const* d_in, const int* in_sizes, int n_in,
                              void* d_out, int out_size) {
    const float* x    = (const float*)d_in[0];
    const void*  ei   = d_in[1];
    const void*  batch= d_in[2];
    const float* b1a  = (const float*)d_in[4];
    const float* b1b  = (const float*)d_in[6];
    const float* b2a  = (const float*)d_in[8];
    const float* b2b  = (const float*)d_in[10];
    const float* Wlin = (const float*)d_in[11];
    const float* blin = (const float*)d_in[12];
    float* out = (float*)d_out;

    __half *fA, *fB, *w16;
    cudaGetSymbolAddress((void**)&fA,  g_fA);
    cudaGetSymbolAddress((void**)&fB,  g_fB);
    cudaGetSymbolAddress((void**)&w16, g_W);

    static cudaStream_t s2;
    static cudaEvent_t e1, e2, e3, e6, e7, e8;
    static int inited = 0;
    if (!inited) {
        cudaStreamCreateWithFlags(&s2, cudaStreamNonBlocking);
        cudaEventCreateWithFlags(&e1, cudaEventDisableTiming);
        cudaEventCreateWithFlags(&e2, cudaEventDisableTiming);
        cudaEventCreateWithFlags(&e3, cudaEventDisableTiming);
        cudaEventCreateWithFlags(&e6, cudaEventDisableTiming);
        cudaEventCreateWithFlags(&e7, cudaEventDisableTiming);
        cudaEventCreateWithFlags(&e8, cudaEventDisableTiming);
        cudaFuncSetAttribute(k_gemm,   cudaFuncAttributeMaxDynamicSharedMemorySize, SMEM_G);
        cudaFuncSetAttribute(k_gemm2x, cudaFuncAttributeMaxDynamicSharedMemorySize, SMEM_G2);
        inited = 1;
    }

    // agg: 2 nodes per warp
    const int aggB0 = ((HALF_N + 1) / 2 * 32 + 255) / 256;
    const int aggB1 = (((N_NODES - HALF_N) + 1) / 2 * 32 + 255) / 256;
    const int poolB0 = (HALF_N + NODES_PER_BLK - 1) / NODES_PER_BLK;
    const int poolB1 = (N_NODES - HALF_N + NODES_PER_BLK - 1) / NODES_PER_BLK;
    const int g2x0 = (NT_H0 + 3) / 4;
    const int g2x1 = (NT - NT_H0 + 3) / 4;

    k_zero1<<<200, 512>>>(ei);
    cudaEventRecord(e1, 0);

    // s0: wprep -> zero2 -> gemm1
    k_wprep<<<(4 * D * D + 255) / 256, 256>>>((const float*)d_in[3], (const float*)d_in[5],
                                              (const float*)d_in[7], (const float*)d_in[9]);
    k_zero2<<<127, 512>>>();
    // s2: CSR chain
    cudaStreamWaitEvent(s2, e1, 0);
    k_hist<<<6250, 256, 0, s2>>>(ei);
    k_gemm<<<NT, 256, SMEM_G>>>(nullptr, x, w16, nullptr, fB, 0, 1, 1, 0, NT);  // u
    cudaEventRecord(e3, 0);
    k_scanlb<<<NB_SCAN, 1024, 0, s2>>>();
    k_fill<<<6250, 256, 0, s2>>>(ei);
    cudaEventRecord(e2, s2);

    // agg1 halves
    cudaStreamWaitEvent(0, e2, 0);
    cudaStreamWaitEvent(s2, e3, 0);
    k_aggbr<<<aggB0, 256>>>(fB, fA, b1a, 0, HALF_N);
    k_aggbr<<<aggB1, 256, 0, s2>>>(fB, fA, b1a, HALF_N, N_NODES);

    // fused gemm2+3 halves
    k_gemm2x<<<g2x0, 256, SMEM_G2>>>(fA, w16 + D * D, w16 + 2 * D * D, b1b, fB, 4, 0, NT_H0);
    cudaEventRecord(e7, 0);
    k_gemm2x<<<g2x1, 256, SMEM_G2, s2>>>(fA, w16 + D * D, w16 + 2 * D * D, b1b, fB, 4, NT_H0, NT);
    cudaEventRecord(e6, s2);

    // agg2 halves
    cudaStreamWaitEvent(0, e6, 0);
    cudaStreamWaitEvent(s2, e7, 0);
    k_aggbr<<<aggB0, 256>>>(fB, fA, b2a, 0, HALF_N);
    k_aggbr<<<aggB1, 256, 0, s2>>>(fB, fA, b2a, HALF_N, N_NODES);

    // gemm4 halves + pool halves
    k_gemm<<<g2x0, 256, SMEM_G>>>(fA, nullptr, w16 + 3 * D * D, b2b, fB, 0, 0, 4, 0, NT_H0);
    k_gemm<<<g2x1, 256, SMEM_G, s2>>>(fA, nullptr, w16 + 3 * D * D, b2b, fB, 0, 0, 4, NT_H0, NT);
    k_pool<<<poolB0, 128>>>(fB, batch, 0, HALF_N);
    k_pool<<<poolB1, 128, 0, s2>>>(fB, batch, HALF_N, N_NODES);
    cudaEventRecord(e8, s2);
    cudaStreamWaitEvent(0, e8, 0);
    k_final<<<N_GRAPHS, 128>>>(Wlin, blin, out);
}